// round 1
// baseline (speedup 1.0000x reference)
#include <cuda_runtime.h>
#include <math.h>

// Problem constants
#define Bb   2
#define Ss   2048
#define Dd   2048
#define Hh   16
#define KVHh 4
#define HDd  128
// N_REP = 4 -> kv head = h >> 2

// Scratch (device globals; no allocation allowed)
__device__ float g_q [(size_t)Bb * Ss * Hh   * HDd];  // rope'd Q  (b,s,h,hd)
__device__ float g_k [(size_t)Bb * Ss * KVHh * HDd];  // rope'd K
__device__ float g_v [(size_t)Bb * Ss * KVHh * HDd];  // V
__device__ float g_t [(size_t)Bb * Ss * Hh   * HDd];  // pre-rope temp
__device__ float g_ao[(size_t)Bb * Ss * Hh   * HDd];  // attention output (b,s, h*hd)

// ---------------------------------------------------------------------------
// SGEMM: C[M,N] = A[M,K] @ B[K,N], all row-major fp32.
// Block tile 128x128, K-step 16, 256 threads, 8x8 micro-tile per thread.
// All dims here are multiples of the tile sizes (M=4096, N in {512,2048}, K=2048).
// ---------------------------------------------------------------------------
__global__ __launch_bounds__(256) void sgemm128(
    const float* __restrict__ A, const float* __restrict__ Bm,
    float* __restrict__ C, int M, int N, int K)
{
    __shared__ float As[16][128];   // transposed A tile: As[k][m]
    __shared__ float Bs[16][128];   // Bs[k][n]

    const int tid  = threadIdx.x;
    const int tr   = tid >> 4;          // 0..15 (row group)
    const int tc   = tid & 15;          // 0..15 (col group)
    const int row0 = blockIdx.y * 128;
    const int col0 = blockIdx.x * 128;

    // A loader: thread covers row (tid>>1), k-cols (tid&1)*8 .. +8
    const int ar = tid >> 1;
    const int ac = (tid & 1) << 3;
    // B loader: thread covers k-row (tid>>4), n-cols (tid&15)*8 .. +8
    const int br = tid >> 4;
    const int bc = (tid & 15) << 3;

    const float* Ap = A  + (size_t)(row0 + ar) * K + ac;
    const float* Bp = Bm + (size_t)br * N + col0 + bc;

    float acc[8][8];
#pragma unroll
    for (int i = 0; i < 8; ++i)
#pragma unroll
        for (int j = 0; j < 8; ++j) acc[i][j] = 0.f;

    const int nk = K >> 4;
    for (int kk = 0; kk < nk; ++kk) {
        float4 a0 = *(const float4*)(Ap);
        float4 a1 = *(const float4*)(Ap + 4);
        float4 b0 = *(const float4*)(Bp);
        float4 b1 = *(const float4*)(Bp + 4);
        __syncthreads();  // previous compute done before overwriting smem
        As[ac + 0][ar] = a0.x; As[ac + 1][ar] = a0.y;
        As[ac + 2][ar] = a0.z; As[ac + 3][ar] = a0.w;
        As[ac + 4][ar] = a1.x; As[ac + 5][ar] = a1.y;
        As[ac + 6][ar] = a1.z; As[ac + 7][ar] = a1.w;
        *(float4*)&Bs[br][bc]     = b0;
        *(float4*)&Bs[br][bc + 4] = b1;
        __syncthreads();
#pragma unroll
        for (int k = 0; k < 16; ++k) {
            float a[8], b[8];
            *(float4*)&a[0] = *(const float4*)&As[k][tr * 8];
            *(float4*)&a[4] = *(const float4*)&As[k][tr * 8 + 4];
            *(float4*)&b[0] = *(const float4*)&Bs[k][tc * 8];
            *(float4*)&b[4] = *(const float4*)&Bs[k][tc * 8 + 4];
#pragma unroll
            for (int i = 0; i < 8; ++i)
#pragma unroll
                for (int j = 0; j < 8; ++j)
                    acc[i][j] += a[i] * b[j];
        }
        Ap += 16;
        Bp += (size_t)16 * N;
    }

#pragma unroll
    for (int i = 0; i < 8; ++i) {
        float* Cp = C + (size_t)(row0 + tr * 8 + i) * N + col0 + tc * 8;
        float4 v0 = make_float4(acc[i][0], acc[i][1], acc[i][2], acc[i][3]);
        float4 v1 = make_float4(acc[i][4], acc[i][5], acc[i][6], acc[i][7]);
        *(float4*)(Cp)     = v0;
        *(float4*)(Cp + 4) = v1;
    }
}

// ---------------------------------------------------------------------------
// RoPE (out-of-place gather form, avoids even/odd in-place race).
// in/out layout: (B*S, nh, 128). cos/sin layout: (S, 64).
// out[i]    = x[2i]*cos[i]   - x[2i+1]*sin[i]     (i < 64)
// out[64+i] = x[2i+1]*cos[i] + x[2i]*sin[i]
// ---------------------------------------------------------------------------
__global__ void rope_kernel(const float* __restrict__ in, float* __restrict__ out,
                            const float* __restrict__ cs, const float* __restrict__ sn,
                            int nh)
{
    int idx = blockIdx.x * blockDim.x + threadIdx.x;
    int total = Bb * Ss * nh * 64;
    if (idx >= total) return;
    int i  = idx & 63;
    int h  = (idx >> 6) % nh;
    int bs = idx / (64 * nh);
    int s  = bs & (Ss - 1);
    float c  = cs[s * 64 + i];
    float s_ = sn[s * 64 + i];
    const float* ri = in  + (size_t)bs * nh * HDd + h * HDd;
    float*       ro = out + (size_t)bs * nh * HDd + h * HDd;
    float p1 = ri[2 * i];
    float p2 = ri[2 * i + 1];
    ro[i]      = p1 * c - p2 * s_;
    ro[64 + i] = p2 * c + p1 * s_;
}

// ---------------------------------------------------------------------------
// Flash attention, causal, GQA. fp32.
// Grid: (S/64, H, B). Block: 256 threads.
// Thread owns rows {r0, r0+32} (r0 = tid>>3) and strided cols {cg + 8*x} (cg = tid&7).
// ---------------------------------------------------------------------------
#define BQ   64
#define BKV  64
#define LSTR 132   // smem row stride for Q/K/V (float4-aligned, bank-decorrelated)
#define PSTR 65    // smem row stride for P

#define ATT_SMEM_BYTES ((3 * BQ * LSTR + BQ * PSTR) * 4)

__device__ __forceinline__ void softmax_update(
    float* s, float& m, float& l, float* o,
    int qglob, int kbase, int cg, bool diag, float* PsRow)
{
    const float scale = 0.08838834764831845f;  // 1/sqrt(128)
    float mx = -1e30f;
#pragma unroll
    for (int j = 0; j < 8; ++j) {
        float v = s[j] * scale;
        if (diag && (kbase + cg + 8 * j) > qglob) v = -1e30f;
        s[j] = v;
        mx = fmaxf(mx, v);
    }
    mx = fmaxf(mx, __shfl_xor_sync(0xffffffffu, mx, 1));
    mx = fmaxf(mx, __shfl_xor_sync(0xffffffffu, mx, 2));
    mx = fmaxf(mx, __shfl_xor_sync(0xffffffffu, mx, 4));
    float mnew = fmaxf(m, mx);
    float sum = 0.f;
#pragma unroll
    for (int j = 0; j < 8; ++j) {
        float p = __expf(s[j] - mnew);
        PsRow[cg + 8 * j] = p;
        sum += p;
    }
    sum += __shfl_xor_sync(0xffffffffu, sum, 1);
    sum += __shfl_xor_sync(0xffffffffu, sum, 2);
    sum += __shfl_xor_sync(0xffffffffu, sum, 4);
    float alpha = __expf(m - mnew);
    l = l * alpha + sum;
#pragma unroll
    for (int c = 0; c < 16; ++c) o[c] *= alpha;
    m = mnew;
}

__global__ __launch_bounds__(256) void flash_attn(
    const float* __restrict__ Qg, const float* __restrict__ Kg,
    const float* __restrict__ Vg, float* __restrict__ Og)
{
    extern __shared__ float sm[];
    float* Qs = sm;
    float* Ks = Qs + BQ * LSTR;
    float* Vs = Ks + BKV * LSTR;
    float* Ps = Vs + BKV * LSTR;

    const int tid   = threadIdx.x;
    const int qt    = blockIdx.x;
    const int h     = blockIdx.y;
    const int b     = blockIdx.z;
    const int kvh   = h >> 2;
    const int qbase = qt * BQ;
    const int r0    = tid >> 3;   // 0..31
    const int cg    = tid & 7;    // 0..7

    // Load Q tile (64 x 128)
#pragma unroll
    for (int i = 0; i < 8; ++i) {
        int idx = tid + i * 256;
        int row = idx >> 5;
        int d4  = (idx & 31) << 2;
        *(float4*)&Qs[row * LSTR + d4] =
            *(const float4*)&Qg[((size_t)(b * Ss + qbase + row) * Hh + h) * HDd + d4];
    }

    float m0 = -1e30f, m1 = -1e30f, l0 = 0.f, l1 = 0.f;
    float o0[16], o1[16];
#pragma unroll
    for (int i = 0; i < 16; ++i) { o0[i] = 0.f; o1[i] = 0.f; }

    for (int kt = 0; kt <= qt; ++kt) {
        const int kbase = kt * BKV;
        __syncthreads();  // previous PV done with Vs/Ps (and Q load visible on iter 0)
#pragma unroll
        for (int i = 0; i < 8; ++i) {
            int idx = tid + i * 256;
            int row = idx >> 5;
            int d4  = (idx & 31) << 2;
            size_t goff = ((size_t)(b * Ss + kbase + row) * KVHh + kvh) * HDd + d4;
            *(float4*)&Ks[row * LSTR + d4] = *(const float4*)&Kg[goff];
            *(float4*)&Vs[row * LSTR + d4] = *(const float4*)&Vg[goff];
        }
        __syncthreads();

        // S = Q K^T for 2 rows x 8 strided cols per thread
        float s0[8], s1[8];
#pragma unroll
        for (int j = 0; j < 8; ++j) { s0[j] = 0.f; s1[j] = 0.f; }
        for (int d4 = 0; d4 < HDd; d4 += 4) {
            float4 q0 = *(const float4*)&Qs[r0 * LSTR + d4];
            float4 q1 = *(const float4*)&Qs[(r0 + 32) * LSTR + d4];
#pragma unroll
            for (int j = 0; j < 8; ++j) {
                float4 k4 = *(const float4*)&Ks[(cg + 8 * j) * LSTR + d4];
                s0[j] += q0.x * k4.x + q0.y * k4.y + q0.z * k4.z + q0.w * k4.w;
                s1[j] += q1.x * k4.x + q1.y * k4.y + q1.z * k4.z + q1.w * k4.w;
            }
        }

        bool diag = (kt == qt);
        softmax_update(s0, m0, l0, o0, qbase + r0,      kbase, cg, diag, &Ps[r0 * PSTR]);
        softmax_update(s1, m1, l1, o1, qbase + r0 + 32, kbase, cg, diag, &Ps[(r0 + 32) * PSTR]);
        __syncthreads();  // Ps written by all before PV reads

        // O += P V
#pragma unroll 8
        for (int k = 0; k < BKV; ++k) {
            float p0 = Ps[r0 * PSTR + k];
            float p1 = Ps[(r0 + 32) * PSTR + k];
#pragma unroll
            for (int c = 0; c < 16; ++c) {
                float vv = Vs[k * LSTR + cg + 8 * c];
                o0[c] += p0 * vv;
                o1[c] += p1 * vv;
            }
        }
    }

    float i0 = 1.f / l0, i1 = 1.f / l1;
#pragma unroll
    for (int c = 0; c < 16; ++c) {
        Og[((size_t)(b * Ss + qbase + r0)      * Hh + h) * HDd + cg + 8 * c] = o0[c] * i0;
        Og[((size_t)(b * Ss + qbase + r0 + 32) * Hh + h) * HDd + cg + 8 * c] = o1[c] * i1;
    }
}

// ---------------------------------------------------------------------------
// Launch: X->QKV GEMMs, RoPE, flash attention, O-proj GEMM.
// Inputs (metadata order): hidden_states, attention_mask, cos, sin, Wq, Wk, Wv, Wo
// attention_mask is exactly causal; implemented directly in the kernel.
// ---------------------------------------------------------------------------
extern "C" void kernel_launch(void* const* d_in, const int* in_sizes, int n_in,
                              void* d_out, int out_size)
{
    const float* X  = (const float*)d_in[0];
    const float* cs = (const float*)d_in[2];
    const float* sn = (const float*)d_in[3];
    const float* Wq = (const float*)d_in[4];
    const float* Wk = (const float*)d_in[5];
    const float* Wv = (const float*)d_in[6];
    const float* Wo = (const float*)d_in[7];
    float* out = (float*)d_out;

    float *gq, *gk, *gv, *gt, *gao;
    cudaGetSymbolAddress((void**)&gq,  g_q);
    cudaGetSymbolAddress((void**)&gk,  g_k);
    cudaGetSymbolAddress((void**)&gv,  g_v);
    cudaGetSymbolAddress((void**)&gt,  g_t);
    cudaGetSymbolAddress((void**)&gao, g_ao);

    const int M = Bb * Ss;  // 4096

    // Q projection -> temp, then RoPE -> g_q
    {
        dim3 grid((Hh * HDd) / 128, M / 128);
        sgemm128<<<grid, 256>>>(X, Wq, gt, M, Hh * HDd, Dd);
        int total = Bb * Ss * Hh * 64;
        rope_kernel<<<(total + 255) / 256, 256>>>(gt, gq, cs, sn, Hh);
    }
    // K projection -> temp, RoPE -> g_k
    {
        dim3 grid((KVHh * HDd) / 128, M / 128);
        sgemm128<<<grid, 256>>>(X, Wk, gt, M, KVHh * HDd, Dd);
        int total = Bb * Ss * KVHh * 64;
        rope_kernel<<<(total + 255) / 256, 256>>>(gt, gk, cs, sn, KVHh);
        // V projection -> g_v (no rope)
        sgemm128<<<grid, 256>>>(X, Wv, gv, M, KVHh * HDd, Dd);
    }
    // Attention
    {
        cudaFuncSetAttribute(flash_attn, cudaFuncAttributeMaxDynamicSharedMemorySize,
                             ATT_SMEM_BYTES);
        dim3 grid(Ss / BQ, Hh, Bb);
        flash_attn<<<grid, 256, ATT_SMEM_BYTES>>>(gq, gk, gv, gao);
    }
    // Output projection -> d_out
    {
        dim3 grid(Dd / 128, M / 128);
        sgemm128<<<grid, 256>>>(gao, Wo, out, M, Dd, Hh * HDd);
    }
}

// round 5
// speedup vs baseline: 1.6332x; 1.6332x over previous
#include <cuda_runtime.h>
#include <cuda_bf16.h>
#include <math.h>
#include <stdint.h>

// Problem constants
#define Bb   2
#define Ss   2048
#define Dd   2048
#define Hh   16
#define KVHh 4
#define HDd  128
#define Mm   (Bb * Ss)   // 4096

// ---------------------------------------------------------------------------
// Scratch (device globals; no allocation allowed). 16B-aligned (vector access).
// ---------------------------------------------------------------------------
__device__ __align__(16) float g_q [(size_t)Mm * Hh   * HDd];
__device__ __align__(16) float g_k [(size_t)Mm * KVHh * HDd];
__device__ __align__(16) float g_v [(size_t)Mm * KVHh * HDd];
__device__ __align__(16) float g_t [(size_t)Mm * Hh   * HDd];
__device__ __align__(16) float g_ao[(size_t)Mm * Hh   * HDd];

__device__ __align__(16) __nv_bfloat16 g_xhi[(size_t)Mm * Dd];
__device__ __align__(16) __nv_bfloat16 g_xlo[(size_t)Mm * Dd];
__device__ __align__(16) __nv_bfloat16 g_wqt_hi[(size_t)Dd * Dd];
__device__ __align__(16) __nv_bfloat16 g_wqt_lo[(size_t)Dd * Dd];
__device__ __align__(16) __nv_bfloat16 g_wkt_hi[(size_t)(KVHh*HDd) * Dd];
__device__ __align__(16) __nv_bfloat16 g_wkt_lo[(size_t)(KVHh*HDd) * Dd];
__device__ __align__(16) __nv_bfloat16 g_wvt_hi[(size_t)(KVHh*HDd) * Dd];
__device__ __align__(16) __nv_bfloat16 g_wvt_lo[(size_t)(KVHh*HDd) * Dd];
__device__ __align__(16) __nv_bfloat16 g_wot_hi[(size_t)Dd * Dd];
__device__ __align__(16) __nv_bfloat16 g_wot_lo[(size_t)Dd * Dd];
__device__ __align__(16) __nv_bfloat16 g_aohi[(size_t)Mm * Dd];
__device__ __align__(16) __nv_bfloat16 g_aolo[(size_t)Mm * Dd];

// ---------------------------------------------------------------------------
// Helpers (all plain PTX, no sm_103a-gated features)
// ---------------------------------------------------------------------------
__device__ __forceinline__ uint32_t smem_u32(const void* p) {
    uint32_t a;
    asm("{ .reg .u64 t; cvta.to.shared.u64 t, %1; cvt.u32.u64 %0, t; }"
        : "=r"(a) : "l"(p));
    return a;
}

__device__ __forceinline__ void cp_async16(uint32_t dst, const void* src) {
    asm volatile("cp.async.cg.shared.global [%0], [%1], 16;" :: "r"(dst), "l"(src));
}
#define CP_COMMIT()  asm volatile("cp.async.commit_group;" ::: "memory")
#define CP_WAIT(n)   asm volatile("cp.async.wait_group %0;" :: "n"(n) : "memory")

__device__ __forceinline__ void ldsm4(uint32_t* r, uint32_t addr) {
    asm volatile("ldmatrix.sync.aligned.m8n8.x4.shared.b16 {%0,%1,%2,%3}, [%4];"
        : "=r"(r[0]), "=r"(r[1]), "=r"(r[2]), "=r"(r[3]) : "r"(addr));
}

__device__ __forceinline__ void mma16816(float* d, const uint32_t* a, const uint32_t* b) {
    asm volatile(
        "mma.sync.aligned.m16n8k16.row.col.f32.bf16.bf16.f32 "
        "{%0,%1,%2,%3}, {%4,%5,%6,%7}, {%8,%9}, {%0,%1,%2,%3};"
        : "+f"(d[0]), "+f"(d[1]), "+f"(d[2]), "+f"(d[3])
        : "r"(a[0]), "r"(a[1]), "r"(a[2]), "r"(a[3]), "r"(b[0]), "r"(b[1]));
}

// ---------------------------------------------------------------------------
// Split fp32 -> (hi, lo) bf16
// ---------------------------------------------------------------------------
__global__ void split_fp32(const float* __restrict__ in,
                           __nv_bfloat16* __restrict__ hi,
                           __nv_bfloat16* __restrict__ lo, int n)
{
    int i = blockIdx.x * blockDim.x + threadIdx.x;
    if (i >= n) return;
    float v = in[i];
    __nv_bfloat16 h = __float2bfloat16(v);
    hi[i] = h;
    lo[i] = __float2bfloat16(v - __bfloat162float(h));
}

// ---------------------------------------------------------------------------
// Transpose + split: fp32 [K,N] row-major -> (hi,lo) bf16 [N,K] row-major
// ---------------------------------------------------------------------------
__global__ __launch_bounds__(256) void transpose_split(
    const float* __restrict__ in, __nv_bfloat16* __restrict__ hiT,
    __nv_bfloat16* __restrict__ loT, int K, int N)
{
    __shared__ float t[32][33];
    int n0 = blockIdx.x * 32, k0 = blockIdx.y * 32;
    int tx = threadIdx.x, ty = threadIdx.y;  // 32 x 8
#pragma unroll
    for (int i = 0; i < 32; i += 8)
        t[ty + i][tx] = in[(size_t)(k0 + ty + i) * N + n0 + tx];
    __syncthreads();
#pragma unroll
    for (int i = 0; i < 32; i += 8) {
        float v = t[tx][ty + i];
        __nv_bfloat16 h = __float2bfloat16(v);
        size_t o = (size_t)(n0 + ty + i) * K + k0 + tx;
        hiT[o] = h;
        loT[o] = __float2bfloat16(v - __bfloat162float(h));
    }
}

// ---------------------------------------------------------------------------
// mma.sync split-bf16 GEMM: C[M,N] = A[M,K] @ B[K,N]  (B supplied as BT[N,K])
// CTA 128x128, 256 thr (8 warps 2x4, warp tile 64x32), BK=32, 2-stage cp.async.
// C ~= Ahi*Bhi + Ahi*Blo + Alo*Bhi
// Smem per stage: Ahi(8K) Alo(8K) BhiT(8K) BloT(8K) = 32KB; x2 stages = 64KB.
// Row = 32 bf16 = 64B = 4 chunks of 16B, swizzle: chunk ^= (row & 3).
// ---------------------------------------------------------------------------
#define GBK 32
#define GSTAGE 32768u
#define GSMEM_BYTES (2 * GSTAGE)

__global__ __launch_bounds__(256) void mma_gemm(
    const __nv_bfloat16* __restrict__ Ahi, const __nv_bfloat16* __restrict__ Alo,
    const __nv_bfloat16* __restrict__ BhiT, const __nv_bfloat16* __restrict__ BloT,
    float* __restrict__ C, int M, int N, int K)
{
    extern __shared__ char sm[];
    const uint32_t sb = smem_u32(sm);
    const int tid  = threadIdx.x;
    const int lane = tid & 31;
    const int wid  = tid >> 5;
    const int row0 = blockIdx.y * 128, col0 = blockIdx.x * 128;
    const int m0 = (wid >> 2) * 64;      // warp m origin in tile
    const int n0 = (wid & 3) * 32;       // warp n origin in tile

    const int k8 = K >> 3;               // uint4 per row
    const uint4* A0 = (const uint4*)Ahi;
    const uint4* A1 = (const uint4*)Alo;
    const uint4* B0 = (const uint4*)BhiT;
    const uint4* B1 = (const uint4*)BloT;

    const int r_ld = tid >> 2;           // 0..63
    const int c_ld = tid & 3;            // chunk 0..3

    auto issue = [&](int c) {
        const uint32_t soff = (c & 1) ? GSTAGE : 0u;
        const int kc = c * 4;            // uint4 base index for this chunk
#pragma unroll
        for (int half = 0; half < 2; ++half) {
            const int row = r_ld + half * 64;
            const uint32_t dst = sb + soff + (uint32_t)row * 64
                               + ((uint32_t)(c_ld ^ (row & 3)) << 4);
            const size_t ia = (size_t)(row0 + row) * k8 + kc + c_ld;
            const size_t ib = (size_t)(col0 + row) * k8 + kc + c_ld;
            cp_async16(dst,          A0 + ia);
            cp_async16(dst +  8192u, A1 + ia);
            cp_async16(dst + 16384u, B0 + ib);
            cp_async16(dst + 24576u, B1 + ib);
        }
        CP_COMMIT();
    };

    float D[4][4][4];
#pragma unroll
    for (int i = 0; i < 4; ++i)
#pragma unroll
        for (int j = 0; j < 4; ++j)
#pragma unroll
            for (int x = 0; x < 4; ++x) D[i][j][x] = 0.f;

    const int nk = K / GBK;
    issue(0);

    // ldmatrix lane geometry
    const int a_rowit = (lane & 7) + ((lane >> 3) & 1) * 8;   // row within m16
    const int a_cb    = lane >> 4;                            // 0/1 k-chunk half
    const int b_rowit = (lane & 7) + ((lane >> 4) << 3);      // row within n16
    const int b_cb    = (lane >> 3) & 1;

    for (int c = 0; c < nk; ++c) {
        if (c + 1 < nk) { issue(c + 1); CP_WAIT(1); }
        else            { CP_WAIT(0); }
        __syncthreads();
        const uint32_t base = sb + ((c & 1) ? GSTAGE : 0u);

#pragma unroll
        for (int ks = 0; ks < 2; ++ks) {                      // two k16 halves
            uint32_t ah[4][4], al[4][4], bh[2][4], bl[2][4];
            const int acb = ks * 2 + a_cb;
            const int bcb = ks * 2 + b_cb;
#pragma unroll
            for (int i = 0; i < 4; ++i) {
                const int r = m0 + 16 * i + a_rowit;
                const uint32_t ad = base + (uint32_t)r * 64
                                  + ((uint32_t)(acb ^ (r & 3)) << 4);
                ldsm4(ah[i], ad);
                ldsm4(al[i], ad + 8192u);
            }
#pragma unroll
            for (int j = 0; j < 2; ++j) {
                const int r = n0 + 16 * j + b_rowit;
                const uint32_t bd = base + 16384u + (uint32_t)r * 64
                                  + ((uint32_t)(bcb ^ (r & 3)) << 4);
                ldsm4(bh[j], bd);
                ldsm4(bl[j], bd + 8192u);
            }
#pragma unroll
            for (int i = 0; i < 4; ++i)
#pragma unroll
                for (int j = 0; j < 2; ++j) {
                    mma16816(D[i][2 * j],     ah[i], bh[j]);      // hi*hi (n8 low)
                    mma16816(D[i][2 * j],     ah[i], bl[j]);      // hi*lo
                    mma16816(D[i][2 * j],     al[i], bh[j]);      // lo*hi
                    mma16816(D[i][2 * j + 1], ah[i], bh[j] + 2);  // n8 high
                    mma16816(D[i][2 * j + 1], ah[i], bl[j] + 2);
                    mma16816(D[i][2 * j + 1], al[i], bh[j] + 2);
                }
        }
        __syncthreads();
    }

    // epilogue: d0,d1 -> (row, col..col+1); d2,d3 -> (row+8, col..col+1)
    const int quad = lane >> 2, tq = lane & 3;
#pragma unroll
    for (int i = 0; i < 4; ++i) {
        const int r = row0 + m0 + 16 * i + quad;
#pragma unroll
        for (int jn = 0; jn < 4; ++jn) {
            const int cc = col0 + n0 + 8 * jn + tq * 2;
            *(float2*)&C[(size_t)r * N + cc]       = make_float2(D[i][jn][0], D[i][jn][1]);
            *(float2*)&C[(size_t)(r + 8) * N + cc] = make_float2(D[i][jn][2], D[i][jn][3]);
        }
    }
}

// ---------------------------------------------------------------------------
// RoPE (out-of-place gather form)
// ---------------------------------------------------------------------------
__global__ void rope_kernel(const float* __restrict__ in, float* __restrict__ out,
                            const float* __restrict__ cs, const float* __restrict__ sn,
                            int nh)
{
    int idx = blockIdx.x * blockDim.x + threadIdx.x;
    int total = Bb * Ss * nh * 64;
    if (idx >= total) return;
    int i  = idx & 63;
    int h  = (idx >> 6) % nh;
    int bs = idx / (64 * nh);
    int s  = bs & (Ss - 1);
    float c  = cs[s * 64 + i];
    float s_ = sn[s * 64 + i];
    const float* ri = in  + (size_t)bs * nh * HDd + h * HDd;
    float*       ro = out + (size_t)bs * nh * HDd + h * HDd;
    float p1 = ri[2 * i];
    float p2 = ri[2 * i + 1];
    ro[i]      = p1 * c - p2 * s_;
    ro[64 + i] = p2 * c + p1 * s_;
}

// ---------------------------------------------------------------------------
// Flash attention, causal, GQA, fp32 (unchanged; known-correct)
// ---------------------------------------------------------------------------
#define BQ   64
#define BKV  64
#define LSTR 132
#define PSTR 65
#define ATT_SMEM_BYTES ((3 * BQ * LSTR + BQ * PSTR) * 4)

__device__ __forceinline__ void softmax_update(
    float* s, float& m, float& l, float* o,
    int qglob, int kbase, int cg, bool diag, float* PsRow)
{
    const float scale = 0.08838834764831845f;
    float mx = -1e30f;
#pragma unroll
    for (int j = 0; j < 8; ++j) {
        float v = s[j] * scale;
        if (diag && (kbase + cg + 8 * j) > qglob) v = -1e30f;
        s[j] = v;
        mx = fmaxf(mx, v);
    }
    mx = fmaxf(mx, __shfl_xor_sync(0xffffffffu, mx, 1));
    mx = fmaxf(mx, __shfl_xor_sync(0xffffffffu, mx, 2));
    mx = fmaxf(mx, __shfl_xor_sync(0xffffffffu, mx, 4));
    float mnew = fmaxf(m, mx);
    float sum = 0.f;
#pragma unroll
    for (int j = 0; j < 8; ++j) {
        float p = __expf(s[j] - mnew);
        PsRow[cg + 8 * j] = p;
        sum += p;
    }
    sum += __shfl_xor_sync(0xffffffffu, sum, 1);
    sum += __shfl_xor_sync(0xffffffffu, sum, 2);
    sum += __shfl_xor_sync(0xffffffffu, sum, 4);
    float alpha = __expf(m - mnew);
    l = l * alpha + sum;
#pragma unroll
    for (int c = 0; c < 16; ++c) o[c] *= alpha;
    m = mnew;
}

__global__ __launch_bounds__(256) void flash_attn(
    const float* __restrict__ Qg, const float* __restrict__ Kg,
    const float* __restrict__ Vg, float* __restrict__ Og)
{
    extern __shared__ float smf[];
    float* Qs = smf;
    float* Ks = Qs + BQ * LSTR;
    float* Vs = Ks + BKV * LSTR;
    float* Ps = Vs + BKV * LSTR;

    const int tid   = threadIdx.x;
    const int qt    = blockIdx.x;
    const int h     = blockIdx.y;
    const int b     = blockIdx.z;
    const int kvh   = h >> 2;
    const int qbase = qt * BQ;
    const int r0    = tid >> 3;
    const int cg    = tid & 7;

#pragma unroll
    for (int i = 0; i < 8; ++i) {
        int idx = tid + i * 256;
        int row = idx >> 5;
        int d4  = (idx & 31) << 2;
        *(float4*)&Qs[row * LSTR + d4] =
            *(const float4*)&Qg[((size_t)(b * Ss + qbase + row) * Hh + h) * HDd + d4];
    }

    float m0 = -1e30f, m1 = -1e30f, l0 = 0.f, l1 = 0.f;
    float o0[16], o1[16];
#pragma unroll
    for (int i = 0; i < 16; ++i) { o0[i] = 0.f; o1[i] = 0.f; }

    for (int kt = 0; kt <= qt; ++kt) {
        const int kbase = kt * BKV;
        __syncthreads();
#pragma unroll
        for (int i = 0; i < 8; ++i) {
            int idx = tid + i * 256;
            int row = idx >> 5;
            int d4  = (idx & 31) << 2;
            size_t goff = ((size_t)(b * Ss + kbase + row) * KVHh + kvh) * HDd + d4;
            *(float4*)&Ks[row * LSTR + d4] = *(const float4*)&Kg[goff];
            *(float4*)&Vs[row * LSTR + d4] = *(const float4*)&Vg[goff];
        }
        __syncthreads();

        float s0[8], s1[8];
#pragma unroll
        for (int j = 0; j < 8; ++j) { s0[j] = 0.f; s1[j] = 0.f; }
        for (int d4 = 0; d4 < HDd; d4 += 4) {
            float4 q0 = *(const float4*)&Qs[r0 * LSTR + d4];
            float4 q1 = *(const float4*)&Qs[(r0 + 32) * LSTR + d4];
#pragma unroll
            for (int j = 0; j < 8; ++j) {
                float4 k4 = *(const float4*)&Ks[(cg + 8 * j) * LSTR + d4];
                s0[j] += q0.x * k4.x + q0.y * k4.y + q0.z * k4.z + q0.w * k4.w;
                s1[j] += q1.x * k4.x + q1.y * k4.y + q1.z * k4.z + q1.w * k4.w;
            }
        }

        bool diag = (kt == qt);
        softmax_update(s0, m0, l0, o0, qbase + r0,      kbase, cg, diag, &Ps[r0 * PSTR]);
        softmax_update(s1, m1, l1, o1, qbase + r0 + 32, kbase, cg, diag, &Ps[(r0 + 32) * PSTR]);
        __syncthreads();

#pragma unroll 8
        for (int k = 0; k < BKV; ++k) {
            float p0 = Ps[r0 * PSTR + k];
            float p1 = Ps[(r0 + 32) * PSTR + k];
#pragma unroll
            for (int c = 0; c < 16; ++c) {
                float vv = Vs[k * LSTR + cg + 8 * c];
                o0[c] += p0 * vv;
                o1[c] += p1 * vv;
            }
        }
    }

    float i0 = 1.f / l0, i1 = 1.f / l1;
#pragma unroll
    for (int c = 0; c < 16; ++c) {
        Og[((size_t)(b * Ss + qbase + r0)      * Hh + h) * HDd + cg + 8 * c] = o0[c] * i0;
        Og[((size_t)(b * Ss + qbase + r0 + 32) * Hh + h) * HDd + cg + 8 * c] = o1[c] * i1;
    }
}

// ---------------------------------------------------------------------------
// Launch. Inputs: hidden_states, attention_mask, cos, sin, Wq, Wk, Wv, Wo
// ---------------------------------------------------------------------------
extern "C" void kernel_launch(void* const* d_in, const int* in_sizes, int n_in,
                              void* d_out, int out_size)
{
    const float* X  = (const float*)d_in[0];
    const float* cs = (const float*)d_in[2];
    const float* sn = (const float*)d_in[3];
    const float* Wq = (const float*)d_in[4];
    const float* Wk = (const float*)d_in[5];
    const float* Wv = (const float*)d_in[6];
    const float* Wo = (const float*)d_in[7];
    float* out = (float*)d_out;

    float *gq, *gk, *gv, *gt, *gao;
    cudaGetSymbolAddress((void**)&gq,  g_q);
    cudaGetSymbolAddress((void**)&gk,  g_k);
    cudaGetSymbolAddress((void**)&gv,  g_v);
    cudaGetSymbolAddress((void**)&gt,  g_t);
    cudaGetSymbolAddress((void**)&gao, g_ao);

    __nv_bfloat16 *xhi, *xlo, *wqh, *wql, *wkh, *wkl, *wvh, *wvl, *woh, *wol, *aoh, *aol;
    cudaGetSymbolAddress((void**)&xhi, g_xhi);
    cudaGetSymbolAddress((void**)&xlo, g_xlo);
    cudaGetSymbolAddress((void**)&wqh, g_wqt_hi);
    cudaGetSymbolAddress((void**)&wql, g_wqt_lo);
    cudaGetSymbolAddress((void**)&wkh, g_wkt_hi);
    cudaGetSymbolAddress((void**)&wkl, g_wkt_lo);
    cudaGetSymbolAddress((void**)&wvh, g_wvt_hi);
    cudaGetSymbolAddress((void**)&wvl, g_wvt_lo);
    cudaGetSymbolAddress((void**)&woh, g_wot_hi);
    cudaGetSymbolAddress((void**)&wol, g_wot_lo);
    cudaGetSymbolAddress((void**)&aoh, g_aohi);
    cudaGetSymbolAddress((void**)&aol, g_aolo);

    cudaFuncSetAttribute(mma_gemm, cudaFuncAttributeMaxDynamicSharedMemorySize, GSMEM_BYTES);
    cudaFuncSetAttribute(flash_attn, cudaFuncAttributeMaxDynamicSharedMemorySize, ATT_SMEM_BYTES);

    // Weight transpose+split and input split
    {
        dim3 blk(32, 8);
        transpose_split<<<dim3(Dd / 32, Dd / 32), blk>>>(Wq, wqh, wql, Dd, Dd);
        transpose_split<<<dim3((KVHh * HDd) / 32, Dd / 32), blk>>>(Wk, wkh, wkl, Dd, KVHh * HDd);
        transpose_split<<<dim3((KVHh * HDd) / 32, Dd / 32), blk>>>(Wv, wvh, wvl, Dd, KVHh * HDd);
        transpose_split<<<dim3(Dd / 32, Dd / 32), blk>>>(Wo, woh, wol, Hh * HDd, Dd);
        int nx = Mm * Dd;
        split_fp32<<<(nx + 255) / 256, 256>>>(X, xhi, xlo, nx);
    }

    // Q projection -> temp, RoPE -> g_q
    mma_gemm<<<dim3((Hh * HDd) / 128, Mm / 128), 256, GSMEM_BYTES>>>(
        xhi, xlo, wqh, wql, gt, Mm, Hh * HDd, Dd);
    rope_kernel<<<(Bb * Ss * Hh * 64 + 255) / 256, 256>>>(gt, gq, cs, sn, Hh);

    // K projection -> temp, RoPE -> g_k
    mma_gemm<<<dim3((KVHh * HDd) / 128, Mm / 128), 256, GSMEM_BYTES>>>(
        xhi, xlo, wkh, wkl, gt, Mm, KVHh * HDd, Dd);
    rope_kernel<<<(Bb * Ss * KVHh * 64 + 255) / 256, 256>>>(gt, gk, cs, sn, KVHh);

    // V projection -> g_v
    mma_gemm<<<dim3((KVHh * HDd) / 128, Mm / 128), 256, GSMEM_BYTES>>>(
        xhi, xlo, wvh, wvl, gv, Mm, KVHh * HDd, Dd);

    // Attention
    flash_attn<<<dim3(Ss / BQ, Hh, Bb), 256, ATT_SMEM_BYTES>>>(gq, gk, gv, gao);

    // Output projection
    {
        int nx = Mm * Dd;
        split_fp32<<<(nx + 255) / 256, 256>>>(gao, aoh, aol, nx);
        mma_gemm<<<dim3(Dd / 128, Mm / 128), 256, GSMEM_BYTES>>>(
            aoh, aol, woh, wol, out, Mm, Dd, Hh * HDd);
    }
}

// round 7
// speedup vs baseline: 3.1781x; 1.9459x over previous
#include <cuda_runtime.h>
#include <cuda_bf16.h>
#include <math.h>
#include <stdint.h>

// Problem constants
#define Bb   2
#define Ss   2048
#define Dd   2048
#define Hh   16
#define KVHh 4
#define HDd  128
#define Mm   (Bb * Ss)   // 4096

// ---------------------------------------------------------------------------
// Scratch (device globals). 16B-aligned (vector access).
// ---------------------------------------------------------------------------
__device__ __align__(16) float g_t [(size_t)Mm * Hh * HDd];   // gemm fp32 temp

__device__ __align__(16) __nv_bfloat16 g_xhi[(size_t)Mm * Dd];
__device__ __align__(16) __nv_bfloat16 g_xlo[(size_t)Mm * Dd];
__device__ __align__(16) __nv_bfloat16 g_wqt_hi[(size_t)Dd * Dd];
__device__ __align__(16) __nv_bfloat16 g_wqt_lo[(size_t)Dd * Dd];
__device__ __align__(16) __nv_bfloat16 g_wkt_hi[(size_t)(KVHh*HDd) * Dd];
__device__ __align__(16) __nv_bfloat16 g_wkt_lo[(size_t)(KVHh*HDd) * Dd];
__device__ __align__(16) __nv_bfloat16 g_wvt_hi[(size_t)(KVHh*HDd) * Dd];
__device__ __align__(16) __nv_bfloat16 g_wvt_lo[(size_t)(KVHh*HDd) * Dd];
__device__ __align__(16) __nv_bfloat16 g_wot_hi[(size_t)Dd * Dd];
__device__ __align__(16) __nv_bfloat16 g_wot_lo[(size_t)Dd * Dd];

__device__ __align__(16) __nv_bfloat16 g_qhi[(size_t)Mm * Hh   * HDd];
__device__ __align__(16) __nv_bfloat16 g_qlo[(size_t)Mm * Hh   * HDd];
__device__ __align__(16) __nv_bfloat16 g_khi[(size_t)Mm * KVHh * HDd];
__device__ __align__(16) __nv_bfloat16 g_klo[(size_t)Mm * KVHh * HDd];
__device__ __align__(16) __nv_bfloat16 g_vhi[(size_t)Mm * KVHh * HDd];
__device__ __align__(16) __nv_bfloat16 g_vlo[(size_t)Mm * KVHh * HDd];
__device__ __align__(16) __nv_bfloat16 g_aohi[(size_t)Mm * Dd];
__device__ __align__(16) __nv_bfloat16 g_aolo[(size_t)Mm * Dd];

// ---------------------------------------------------------------------------
// Helpers (plain PTX, nothing sm_103a-gated)
// ---------------------------------------------------------------------------
__device__ __forceinline__ uint32_t smem_u32(const void* p) {
    uint32_t a;
    asm("{ .reg .u64 t; cvta.to.shared.u64 t, %1; cvt.u32.u64 %0, t; }"
        : "=r"(a) : "l"(p));
    return a;
}
__device__ __forceinline__ void cp_async16(uint32_t dst, const void* src) {
    asm volatile("cp.async.cg.shared.global [%0], [%1], 16;" :: "r"(dst), "l"(src));
}
#define CP_COMMIT()  asm volatile("cp.async.commit_group;" ::: "memory")
#define CP_WAIT(n)   asm volatile("cp.async.wait_group %0;" :: "n"(n) : "memory")

__device__ __forceinline__ void ldsm4(uint32_t* r, uint32_t addr) {
    asm volatile("ldmatrix.sync.aligned.m8n8.x4.shared.b16 {%0,%1,%2,%3}, [%4];"
        : "=r"(r[0]), "=r"(r[1]), "=r"(r[2]), "=r"(r[3]) : "r"(addr));
}
__device__ __forceinline__ void ldsm4t(uint32_t* r, uint32_t addr) {
    asm volatile("ldmatrix.sync.aligned.m8n8.x4.trans.shared.b16 {%0,%1,%2,%3}, [%4];"
        : "=r"(r[0]), "=r"(r[1]), "=r"(r[2]), "=r"(r[3]) : "r"(addr));
}
__device__ __forceinline__ void mma16816(float* d, const uint32_t* a, const uint32_t* b) {
    asm volatile(
        "mma.sync.aligned.m16n8k16.row.col.f32.bf16.bf16.f32 "
        "{%0,%1,%2,%3}, {%4,%5,%6,%7}, {%8,%9}, {%0,%1,%2,%3};"
        : "+f"(d[0]), "+f"(d[1]), "+f"(d[2]), "+f"(d[3])
        : "r"(a[0]), "r"(a[1]), "r"(a[2]), "r"(a[3]), "r"(b[0]), "r"(b[1]));
}
__device__ __forceinline__ uint32_t bf2u(__nv_bfloat162 v) {
    return *reinterpret_cast<uint32_t*>(&v);
}

// ---------------------------------------------------------------------------
// Split fp32 -> (hi, lo) bf16
// ---------------------------------------------------------------------------
__global__ void split_fp32(const float* __restrict__ in,
                           __nv_bfloat16* __restrict__ hi,
                           __nv_bfloat16* __restrict__ lo, int n)
{
    int i = blockIdx.x * blockDim.x + threadIdx.x;
    if (i >= n) return;
    float v = in[i];
    __nv_bfloat16 h = __float2bfloat16(v);
    hi[i] = h;
    lo[i] = __float2bfloat16(v - __bfloat162float(h));
}

// ---------------------------------------------------------------------------
// Transpose + split: fp32 [K,N] row-major -> (hi,lo) bf16 [N,K] row-major
// ---------------------------------------------------------------------------
__global__ __launch_bounds__(256) void transpose_split(
    const float* __restrict__ in, __nv_bfloat16* __restrict__ hiT,
    __nv_bfloat16* __restrict__ loT, int K, int N)
{
    __shared__ float t[32][33];
    int n0 = blockIdx.x * 32, k0 = blockIdx.y * 32;
    int tx = threadIdx.x, ty = threadIdx.y;  // 32 x 8
#pragma unroll
    for (int i = 0; i < 32; i += 8)
        t[ty + i][tx] = in[(size_t)(k0 + ty + i) * N + n0 + tx];
    __syncthreads();
#pragma unroll
    for (int i = 0; i < 32; i += 8) {
        float v = t[tx][ty + i];
        __nv_bfloat16 h = __float2bfloat16(v);
        size_t o = (size_t)(n0 + ty + i) * K + k0 + tx;
        hiT[o] = h;
        loT[o] = __float2bfloat16(v - __bfloat162float(h));
    }
}

// ---------------------------------------------------------------------------
// mma.sync split-bf16 GEMM — EXACT R5-verified fragment geometry.
// C[M,N] = A[M,K] @ B[K,N] (B supplied as BT[N,K]); optional split-bf16 out.
// ---------------------------------------------------------------------------
#define GBK 32
#define GSTAGE 32768u
#define GSMEM_BYTES (2 * GSTAGE)

__global__ __launch_bounds__(256) void mma_gemm(
    const __nv_bfloat16* __restrict__ Ahi, const __nv_bfloat16* __restrict__ Alo,
    const __nv_bfloat16* __restrict__ BhiT, const __nv_bfloat16* __restrict__ BloT,
    float* __restrict__ C,
    __nv_bfloat16* __restrict__ Chi, __nv_bfloat16* __restrict__ Clo,
    int M, int N, int K)
{
    extern __shared__ char sm[];
    const uint32_t sb = smem_u32(sm);
    const int tid  = threadIdx.x;
    const int lane = tid & 31;
    const int wid  = tid >> 5;
    const int row0 = blockIdx.y * 128, col0 = blockIdx.x * 128;
    const int m0 = (wid >> 2) * 64;
    const int n0 = (wid & 3) * 32;

    const int k8 = K >> 3;
    const uint4* A0 = (const uint4*)Ahi;
    const uint4* A1 = (const uint4*)Alo;
    const uint4* B0 = (const uint4*)BhiT;
    const uint4* B1 = (const uint4*)BloT;

    const int r_ld = tid >> 2;
    const int c_ld = tid & 3;

    auto issue = [&](int c) {
        const uint32_t soff = (c & 1) ? GSTAGE : 0u;
        const int kc = c * 4;
#pragma unroll
        for (int half = 0; half < 2; ++half) {
            const int row = r_ld + half * 64;
            const uint32_t dst = sb + soff + (uint32_t)row * 64
                               + ((uint32_t)(c_ld ^ (row & 3)) << 4);
            const size_t ia = (size_t)(row0 + row) * k8 + kc + c_ld;
            const size_t ib = (size_t)(col0 + row) * k8 + kc + c_ld;
            cp_async16(dst,          A0 + ia);
            cp_async16(dst +  8192u, A1 + ia);
            cp_async16(dst + 16384u, B0 + ib);
            cp_async16(dst + 24576u, B1 + ib);
        }
        CP_COMMIT();
    };

    float D[4][4][4];
#pragma unroll
    for (int i = 0; i < 4; ++i)
#pragma unroll
        for (int j = 0; j < 4; ++j)
#pragma unroll
            for (int x = 0; x < 4; ++x) D[i][j][x] = 0.f;

    const int nk = K / GBK;
    issue(0);

    // R5-verified lane geometry
    const int a_rowit = (lane & 7) + ((lane >> 3) & 1) * 8;   // row within m16
    const int a_cb    = lane >> 4;                            // k-chunk half
    const int b_rowit = (lane & 7) + ((lane >> 4) << 3);      // row within n16
    const int b_cb    = (lane >> 3) & 1;

    for (int c = 0; c < nk; ++c) {
        if (c + 1 < nk) { issue(c + 1); CP_WAIT(1); }
        else            { CP_WAIT(0); }
        __syncthreads();
        const uint32_t base = sb + ((c & 1) ? GSTAGE : 0u);

#pragma unroll
        for (int ks = 0; ks < 2; ++ks) {
            uint32_t ah[4][4], al[4][4], bh[2][4], bl[2][4];
            const int acb = ks * 2 + a_cb;
            const int bcb = ks * 2 + b_cb;
#pragma unroll
            for (int i = 0; i < 4; ++i) {
                const int r = m0 + 16 * i + a_rowit;
                const uint32_t ad = base + (uint32_t)r * 64
                                  + ((uint32_t)(acb ^ (r & 3)) << 4);
                ldsm4(ah[i], ad);
                ldsm4(al[i], ad + 8192u);
            }
#pragma unroll
            for (int j = 0; j < 2; ++j) {
                const int r = n0 + 16 * j + b_rowit;
                const uint32_t bd = base + 16384u + (uint32_t)r * 64
                                  + ((uint32_t)(bcb ^ (r & 3)) << 4);
                ldsm4(bh[j], bd);
                ldsm4(bl[j], bd + 8192u);
            }
#pragma unroll
            for (int i = 0; i < 4; ++i)
#pragma unroll
                for (int j = 0; j < 2; ++j) {
                    mma16816(D[i][2 * j],     ah[i], bh[j]);      // n8 low: {r0,r1}
                    mma16816(D[i][2 * j],     ah[i], bl[j]);
                    mma16816(D[i][2 * j],     al[i], bh[j]);
                    mma16816(D[i][2 * j + 1], ah[i], bh[j] + 2);  // n8 high: {r2,r3}
                    mma16816(D[i][2 * j + 1], ah[i], bl[j] + 2);
                    mma16816(D[i][2 * j + 1], al[i], bh[j] + 2);
                }
        }
        __syncthreads();
    }

    const int quad = lane >> 2, tq = lane & 3;
#pragma unroll
    for (int i = 0; i < 4; ++i) {
        const int r = row0 + m0 + 16 * i + quad;
#pragma unroll
        for (int jn = 0; jn < 4; ++jn) {
            const int cc = col0 + n0 + 8 * jn + tq * 2;
            if (Chi) {
#pragma unroll
                for (int hh = 0; hh < 2; ++hh) {   // row r, r+8
                    float v0 = D[i][jn][2 * hh], v1 = D[i][jn][2 * hh + 1];
                    __nv_bfloat162 h01 = __floats2bfloat162_rn(v0, v1);
                    __nv_bfloat162 l01 = __floats2bfloat162_rn(
                        v0 - __low2float(h01), v1 - __high2float(h01));
                    size_t o = (size_t)(r + 8 * hh) * N + cc;
                    *(uint32_t*)(Chi + o) = bf2u(h01);
                    *(uint32_t*)(Clo + o) = bf2u(l01);
                }
            } else {
                *(float2*)&C[(size_t)r * N + cc]       = make_float2(D[i][jn][0], D[i][jn][1]);
                *(float2*)&C[(size_t)(r + 8) * N + cc] = make_float2(D[i][jn][2], D[i][jn][3]);
            }
        }
    }
}

// ---------------------------------------------------------------------------
// RoPE -> split bf16 (hi, lo)
// ---------------------------------------------------------------------------
__global__ void rope_split(const float* __restrict__ in,
                           __nv_bfloat16* __restrict__ hi, __nv_bfloat16* __restrict__ lo,
                           const float* __restrict__ cs, const float* __restrict__ sn,
                           int nh)
{
    int idx = blockIdx.x * blockDim.x + threadIdx.x;
    int total = Bb * Ss * nh * 64;
    if (idx >= total) return;
    int i  = idx & 63;
    int h  = (idx >> 6) % nh;
    int bs = idx / (64 * nh);
    int s  = bs & (Ss - 1);
    float c  = cs[s * 64 + i];
    float s_ = sn[s * 64 + i];
    const float* ri = in + (size_t)bs * nh * HDd + h * HDd;
    size_t ro = (size_t)bs * nh * HDd + h * HDd;
    float p1 = ri[2 * i];
    float p2 = ri[2 * i + 1];
    float r1 = p1 * c - p2 * s_;
    float r2 = p2 * c + p1 * s_;
    __nv_bfloat16 h1 = __float2bfloat16(r1);
    __nv_bfloat16 h2 = __float2bfloat16(r2);
    hi[ro + i]      = h1;
    hi[ro + 64 + i] = h2;
    lo[ro + i]      = __float2bfloat16(r1 - __bfloat162float(h1));
    lo[ro + 64 + i] = __float2bfloat16(r2 - __bfloat162float(h2));
}

// ---------------------------------------------------------------------------
// Flash attention on mma.sync, split-bf16 for QK^T and PV. Causal, GQA.
// CTA: q-tile 128 rows, 256 threads (8 warps x m16). KV tiles 64, dbl-buffered.
// Smem rows = 128 bf16 = 256B = 16 chunks, swizzle c^(r&7).
// ---------------------------------------------------------------------------
#define ASWZ(r, c) ((uint32_t)(r) * 256u + ((uint32_t)((c) ^ ((r) & 7)) << 4))
#define ASM_QLO   32768u
#define ASM_STAGE 65536u
#define ASMEM_BYTES 196608

__global__ __launch_bounds__(256) void flash_attn_mma(
    const __nv_bfloat16* __restrict__ Qhi, const __nv_bfloat16* __restrict__ Qlo,
    const __nv_bfloat16* __restrict__ Khi, const __nv_bfloat16* __restrict__ Klo,
    const __nv_bfloat16* __restrict__ Vhi, const __nv_bfloat16* __restrict__ Vlo,
    __nv_bfloat16* __restrict__ AOhi, __nv_bfloat16* __restrict__ AOlo)
{
    extern __shared__ char sm[];
    const uint32_t sb = smem_u32(sm);
    const int tid = threadIdx.x, lane = tid & 31, wid = tid >> 5;
    const int qt = (int)gridDim.x - 1 - (int)blockIdx.x;   // heavy tiles first
    const int h = blockIdx.y, b = blockIdx.z, kvh = h >> 2;
    const int q0 = qt * 128;
    const int m0 = wid * 16;
    const int nkt = 2 * qt + 2;

    const int c_ld = tid & 15, r_ld = tid >> 4;

    // Q tile (128 x 128, hi+lo)
#pragma unroll
    for (int i = 0; i < 8; ++i) {
        int r = r_ld + 16 * i;
        size_t g = ((size_t)((b * Ss + q0 + r) * Hh + h)) * HDd + c_ld * 8;
        uint32_t d = sb + ASWZ(r, c_ld);
        cp_async16(d,           Qhi + g);
        cp_async16(d + ASM_QLO, Qlo + g);
    }
    auto issue_kv = [&](int kt) {
        uint32_t st = sb + ASM_STAGE + (uint32_t)(kt & 1) * 65536u;
        int kbase = kt * 64;
#pragma unroll
        for (int i = 0; i < 4; ++i) {
            int r = r_ld + 16 * i;
            size_t g = ((size_t)((b * Ss + kbase + r) * KVHh + kvh)) * HDd + c_ld * 8;
            uint32_t d = ASWZ(r, c_ld);
            cp_async16(st + d,          Khi + g);
            cp_async16(st + 16384u + d, Klo + g);
            cp_async16(st + 32768u + d, Vhi + g);
            cp_async16(st + 49152u + d, Vlo + g);
        }
    };
    issue_kv(0);
    CP_COMMIT();

    float O[16][4];
#pragma unroll
    for (int i = 0; i < 16; ++i)
#pragma unroll
        for (int x = 0; x < 4; ++x) O[i][x] = 0.f;
    float m_lo = -1e30f, m_hi = -1e30f, l_lo = 0.f, l_hi = 0.f;

    const int quad = lane >> 2, tq = lane & 3;
    const int rit = lane & 15;
    const int chalf = lane >> 4;
    const int row_lo = q0 + m0 + quad;
    const int row_hi = row_lo + 8;
    const float scale = 0.08838834764831845f;

    for (int kt = 0; kt < nkt; ++kt) {
        if (kt + 1 < nkt) { issue_kv(kt + 1); CP_COMMIT(); CP_WAIT(1); }
        else              { CP_WAIT(0); }
        __syncthreads();

        const int kbase = kt * 64;
        if (kbase <= q0 + m0 + 15) {
            const uint32_t sK = sb + ASM_STAGE + (uint32_t)(kt & 1) * 65536u;
            const uint32_t sV = sK + 32768u;

            float S[8][4];
#pragma unroll
            for (int i = 0; i < 8; ++i)
#pragma unroll
                for (int x = 0; x < 4; ++x) S[i][x] = 0.f;

#pragma unroll
            for (int k16 = 0; k16 < 8; ++k16) {
                uint32_t qh[4], ql[4];
                uint32_t qa = sb + ASWZ(m0 + rit, k16 * 2 + chalf);
                ldsm4(qh, qa);
                ldsm4(ql, qa + ASM_QLO);
#pragma unroll
                for (int np = 0; np < 4; ++np) {
                    uint32_t kh[4], kl[4];
                    uint32_t ka = ASWZ(np * 16 + rit, k16 * 2 + chalf);
                    ldsm4(kh, sK + ka);
                    ldsm4(kl, sK + 16384u + ka);
                    uint32_t bh0[2] = {kh[0], kh[2]}, bh1[2] = {kh[1], kh[3]};
                    uint32_t bl0[2] = {kl[0], kl[2]}, bl1[2] = {kl[1], kl[3]};
                    mma16816(S[2 * np],     qh, bh0);
                    mma16816(S[2 * np],     qh, bl0);
                    mma16816(S[2 * np],     ql, bh0);
                    mma16816(S[2 * np + 1], qh, bh1);
                    mma16816(S[2 * np + 1], qh, bl1);
                    mma16816(S[2 * np + 1], ql, bh1);
                }
            }

            // online softmax
            const bool do_mask = (kt >= nkt - 2);
            float tmx_lo = -1e30f, tmx_hi = -1e30f;
#pragma unroll
            for (int nb = 0; nb < 8; ++nb) {
                int c0 = kbase + nb * 8 + tq * 2;
                float v0 = S[nb][0] * scale, v1 = S[nb][1] * scale;
                float v2 = S[nb][2] * scale, v3 = S[nb][3] * scale;
                if (do_mask) {
                    if (c0     > row_lo) v0 = -1e30f;
                    if (c0 + 1 > row_lo) v1 = -1e30f;
                    if (c0     > row_hi) v2 = -1e30f;
                    if (c0 + 1 > row_hi) v3 = -1e30f;
                }
                S[nb][0] = v0; S[nb][1] = v1; S[nb][2] = v2; S[nb][3] = v3;
                tmx_lo = fmaxf(tmx_lo, fmaxf(v0, v1));
                tmx_hi = fmaxf(tmx_hi, fmaxf(v2, v3));
            }
            tmx_lo = fmaxf(tmx_lo, __shfl_xor_sync(0xffffffffu, tmx_lo, 1));
            tmx_lo = fmaxf(tmx_lo, __shfl_xor_sync(0xffffffffu, tmx_lo, 2));
            tmx_hi = fmaxf(tmx_hi, __shfl_xor_sync(0xffffffffu, tmx_hi, 1));
            tmx_hi = fmaxf(tmx_hi, __shfl_xor_sync(0xffffffffu, tmx_hi, 2));
            float mn_lo = fmaxf(m_lo, tmx_lo), mn_hi = fmaxf(m_hi, tmx_hi);
            float a_lo = __expf(m_lo - mn_lo), a_hi = __expf(m_hi - mn_hi);
            m_lo = mn_lo; m_hi = mn_hi;
            float s_lo = 0.f, s_hi = 0.f;
#pragma unroll
            for (int nb = 0; nb < 8; ++nb) {
                S[nb][0] = __expf(S[nb][0] - mn_lo);
                S[nb][1] = __expf(S[nb][1] - mn_lo);
                S[nb][2] = __expf(S[nb][2] - mn_hi);
                S[nb][3] = __expf(S[nb][3] - mn_hi);
                s_lo += S[nb][0] + S[nb][1];
                s_hi += S[nb][2] + S[nb][3];
            }
            s_lo += __shfl_xor_sync(0xffffffffu, s_lo, 1);
            s_lo += __shfl_xor_sync(0xffffffffu, s_lo, 2);
            s_hi += __shfl_xor_sync(0xffffffffu, s_hi, 1);
            s_hi += __shfl_xor_sync(0xffffffffu, s_hi, 2);
            l_lo = l_lo * a_lo + s_lo;
            l_hi = l_hi * a_hi + s_hi;
#pragma unroll
            for (int nb = 0; nb < 16; ++nb) {
                O[nb][0] *= a_lo; O[nb][1] *= a_lo;
                O[nb][2] *= a_hi; O[nb][3] *= a_hi;
            }

            // P fragments (split)
            uint32_t ph[4][4], pl[4][4];
#pragma unroll
            for (int kb = 0; kb < 4; ++kb) {
#pragma unroll
                for (int hf = 0; hf < 2; ++hf) {
                    int nb = 2 * kb + hf;
                    __nv_bfloat162 h01 = __floats2bfloat162_rn(S[nb][0], S[nb][1]);
                    __nv_bfloat162 h23 = __floats2bfloat162_rn(S[nb][2], S[nb][3]);
                    __nv_bfloat162 l01 = __floats2bfloat162_rn(
                        S[nb][0] - __low2float(h01), S[nb][1] - __high2float(h01));
                    __nv_bfloat162 l23 = __floats2bfloat162_rn(
                        S[nb][2] - __low2float(h23), S[nb][3] - __high2float(h23));
                    ph[kb][2 * hf]     = bf2u(h01);
                    ph[kb][2 * hf + 1] = bf2u(h23);
                    pl[kb][2 * hf]     = bf2u(l01);
                    pl[kb][2 * hf + 1] = bf2u(l23);
                }
            }

            // O += P V (V via ldmatrix.trans)
#pragma unroll
            for (int kb = 0; kb < 4; ++kb) {
#pragma unroll
                for (int np2 = 0; np2 < 8; ++np2) {
                    uint32_t vh[4], vl[4];
                    uint32_t va = ASWZ(kb * 16 + rit, np2 * 2 + chalf);
                    ldsm4t(vh, sV + va);
                    ldsm4t(vl, sV + 16384u + va);
                    uint32_t bh0[2] = {vh[0], vh[1]}, bh1[2] = {vh[2], vh[3]};
                    uint32_t bl0[2] = {vl[0], vl[1]}, bl1[2] = {vl[2], vl[3]};
                    mma16816(O[2 * np2],     ph[kb], bh0);
                    mma16816(O[2 * np2],     ph[kb], bl0);
                    mma16816(O[2 * np2],     pl[kb], bh0);
                    mma16816(O[2 * np2 + 1], ph[kb], bh1);
                    mma16816(O[2 * np2 + 1], ph[kb], bl1);
                    mma16816(O[2 * np2 + 1], pl[kb], bh1);
                }
            }
        }
        __syncthreads();
    }

    // epilogue: write bf16 split AO [Mm, 2048]
    float i_lo = 1.f / l_lo, i_hi = 1.f / l_hi;
#pragma unroll
    for (int nb = 0; nb < 16; ++nb) {
        float v0 = O[nb][0] * i_lo, v1 = O[nb][1] * i_lo;
        float v2 = O[nb][2] * i_hi, v3 = O[nb][3] * i_hi;
        size_t o_lo = (size_t)(b * Ss + row_lo) * Dd + h * HDd + nb * 8 + tq * 2;
        size_t o_hi = o_lo + 8 * (size_t)Dd;
        __nv_bfloat162 h01 = __floats2bfloat162_rn(v0, v1);
        __nv_bfloat162 l01 = __floats2bfloat162_rn(v0 - __low2float(h01), v1 - __high2float(h01));
        __nv_bfloat162 h23 = __floats2bfloat162_rn(v2, v3);
        __nv_bfloat162 l23 = __floats2bfloat162_rn(v2 - __low2float(h23), v3 - __high2float(h23));
        *(uint32_t*)(AOhi + o_lo) = bf2u(h01);
        *(uint32_t*)(AOlo + o_lo) = bf2u(l01);
        *(uint32_t*)(AOhi + o_hi) = bf2u(h23);
        *(uint32_t*)(AOlo + o_hi) = bf2u(l23);
    }
}

// ---------------------------------------------------------------------------
// Launch. Inputs: hidden_states, attention_mask, cos, sin, Wq, Wk, Wv, Wo
// ---------------------------------------------------------------------------
extern "C" void kernel_launch(void* const* d_in, const int* in_sizes, int n_in,
                              void* d_out, int out_size)
{
    const float* X  = (const float*)d_in[0];
    const float* cs = (const float*)d_in[2];
    const float* sn = (const float*)d_in[3];
    const float* Wq = (const float*)d_in[4];
    const float* Wk = (const float*)d_in[5];
    const float* Wv = (const float*)d_in[6];
    const float* Wo = (const float*)d_in[7];
    float* out = (float*)d_out;

    float* gt;
    cudaGetSymbolAddress((void**)&gt, g_t);

    __nv_bfloat16 *xhi, *xlo, *wqh, *wql, *wkh, *wkl, *wvh, *wvl, *woh, *wol;
    __nv_bfloat16 *qhi, *qlo, *khi, *klo, *vhi, *vlo, *aoh, *aol;
    cudaGetSymbolAddress((void**)&xhi, g_xhi);
    cudaGetSymbolAddress((void**)&xlo, g_xlo);
    cudaGetSymbolAddress((void**)&wqh, g_wqt_hi);
    cudaGetSymbolAddress((void**)&wql, g_wqt_lo);
    cudaGetSymbolAddress((void**)&wkh, g_wkt_hi);
    cudaGetSymbolAddress((void**)&wkl, g_wkt_lo);
    cudaGetSymbolAddress((void**)&wvh, g_wvt_hi);
    cudaGetSymbolAddress((void**)&wvl, g_wvt_lo);
    cudaGetSymbolAddress((void**)&woh, g_wot_hi);
    cudaGetSymbolAddress((void**)&wol, g_wot_lo);
    cudaGetSymbolAddress((void**)&qhi, g_qhi);
    cudaGetSymbolAddress((void**)&qlo, g_qlo);
    cudaGetSymbolAddress((void**)&khi, g_khi);
    cudaGetSymbolAddress((void**)&klo, g_klo);
    cudaGetSymbolAddress((void**)&vhi, g_vhi);
    cudaGetSymbolAddress((void**)&vlo, g_vlo);
    cudaGetSymbolAddress((void**)&aoh, g_aohi);
    cudaGetSymbolAddress((void**)&aol, g_aolo);

    cudaFuncSetAttribute(mma_gemm, cudaFuncAttributeMaxDynamicSharedMemorySize, GSMEM_BYTES);
    cudaFuncSetAttribute(flash_attn_mma, cudaFuncAttributeMaxDynamicSharedMemorySize, ASMEM_BYTES);

    // Weight transpose+split and input split
    {
        dim3 blk(32, 8);
        transpose_split<<<dim3(Dd / 32, Dd / 32), blk>>>(Wq, wqh, wql, Dd, Dd);
        transpose_split<<<dim3((KVHh * HDd) / 32, Dd / 32), blk>>>(Wk, wkh, wkl, Dd, KVHh * HDd);
        transpose_split<<<dim3((KVHh * HDd) / 32, Dd / 32), blk>>>(Wv, wvh, wvl, Dd, KVHh * HDd);
        transpose_split<<<dim3(Dd / 32, Dd / 32), blk>>>(Wo, woh, wol, Hh * HDd, Dd);
        int nx = Mm * Dd;
        split_fp32<<<(nx + 255) / 256, 256>>>(X, xhi, xlo, nx);
    }

    // Q projection -> temp, RoPE -> split bf16
    mma_gemm<<<dim3((Hh * HDd) / 128, Mm / 128), 256, GSMEM_BYTES>>>(
        xhi, xlo, wqh, wql, gt, nullptr, nullptr, Mm, Hh * HDd, Dd);
    rope_split<<<(Bb * Ss * Hh * 64 + 255) / 256, 256>>>(gt, qhi, qlo, cs, sn, Hh);

    // K projection -> temp, RoPE -> split bf16
    mma_gemm<<<dim3((KVHh * HDd) / 128, Mm / 128), 256, GSMEM_BYTES>>>(
        xhi, xlo, wkh, wkl, gt, nullptr, nullptr, Mm, KVHh * HDd, Dd);
    rope_split<<<(Bb * Ss * KVHh * 64 + 255) / 256, 256>>>(gt, khi, klo, cs, sn, KVHh);

    // V projection -> split bf16 directly
    mma_gemm<<<dim3((KVHh * HDd) / 128, Mm / 128), 256, GSMEM_BYTES>>>(
        xhi, xlo, wvh, wvl, nullptr, vhi, vlo, Mm, KVHh * HDd, Dd);

    // Attention (tensor-core, split bf16), writes split AO directly
    flash_attn_mma<<<dim3(Ss / 128, Hh, Bb), 256, ASMEM_BYTES>>>(
        qhi, qlo, khi, klo, vhi, vlo, aoh, aol);

    // Output projection -> fp32 out
    mma_gemm<<<dim3(Dd / 128, Mm / 128), 256, GSMEM_BYTES>>>(
        aoh, aol, woh, wol, out, nullptr, nullptr, Mm, Dd, Hh * HDd);
}

// round 10
// speedup vs baseline: 3.4971x; 1.1004x over previous
#include <cuda_runtime.h>
#include <cuda_bf16.h>
#include <math.h>
#include <stdint.h>

// Problem constants
#define Bb   2
#define Ss   2048
#define Dd   2048
#define Hh   16
#define KVHh 4
#define HDd  128
#define Mm   (Bb * Ss)   // 4096

// ---------------------------------------------------------------------------
// Scratch (device globals). 16B-aligned (vector access).
// ---------------------------------------------------------------------------
__device__ __align__(16) __nv_bfloat16 g_xhi[(size_t)Mm * Dd];
__device__ __align__(16) __nv_bfloat16 g_xlo[(size_t)Mm * Dd];
__device__ __align__(16) __nv_bfloat16 g_wqt_hi[(size_t)Dd * Dd];
__device__ __align__(16) __nv_bfloat16 g_wqt_lo[(size_t)Dd * Dd];
__device__ __align__(16) __nv_bfloat16 g_wkt_hi[(size_t)(KVHh*HDd) * Dd];
__device__ __align__(16) __nv_bfloat16 g_wkt_lo[(size_t)(KVHh*HDd) * Dd];
__device__ __align__(16) __nv_bfloat16 g_wvt_hi[(size_t)(KVHh*HDd) * Dd];
__device__ __align__(16) __nv_bfloat16 g_wvt_lo[(size_t)(KVHh*HDd) * Dd];
__device__ __align__(16) __nv_bfloat16 g_wot_hi[(size_t)Dd * Dd];
__device__ __align__(16) __nv_bfloat16 g_wot_lo[(size_t)Dd * Dd];

__device__ __align__(16) __nv_bfloat16 g_qhi[(size_t)Mm * Hh   * HDd];
__device__ __align__(16) __nv_bfloat16 g_qlo[(size_t)Mm * Hh   * HDd];
__device__ __align__(16) __nv_bfloat16 g_khi[(size_t)Mm * KVHh * HDd];
__device__ __align__(16) __nv_bfloat16 g_klo[(size_t)Mm * KVHh * HDd];
__device__ __align__(16) __nv_bfloat16 g_vhi[(size_t)Mm * KVHh * HDd];
__device__ __align__(16) __nv_bfloat16 g_vlo[(size_t)Mm * KVHh * HDd];
__device__ __align__(16) __nv_bfloat16 g_aohi[(size_t)Mm * Dd];
__device__ __align__(16) __nv_bfloat16 g_aolo[(size_t)Mm * Dd];

// ---------------------------------------------------------------------------
// Helpers (plain PTX, nothing sm_103a-gated)
// ---------------------------------------------------------------------------
__device__ __forceinline__ uint32_t smem_u32(const void* p) {
    uint32_t a;
    asm("{ .reg .u64 t; cvta.to.shared.u64 t, %1; cvt.u32.u64 %0, t; }"
        : "=r"(a) : "l"(p));
    return a;
}
__device__ __forceinline__ void cp_async16(uint32_t dst, const void* src) {
    asm volatile("cp.async.cg.shared.global [%0], [%1], 16;" :: "r"(dst), "l"(src));
}
#define CP_COMMIT()  asm volatile("cp.async.commit_group;" ::: "memory")
#define CP_WAIT(n)   asm volatile("cp.async.wait_group %0;" :: "n"(n) : "memory")

__device__ __forceinline__ void ldsm4(uint32_t* r, uint32_t addr) {
    asm volatile("ldmatrix.sync.aligned.m8n8.x4.shared.b16 {%0,%1,%2,%3}, [%4];"
        : "=r"(r[0]), "=r"(r[1]), "=r"(r[2]), "=r"(r[3]) : "r"(addr));
}
__device__ __forceinline__ void ldsm4t(uint32_t* r, uint32_t addr) {
    asm volatile("ldmatrix.sync.aligned.m8n8.x4.trans.shared.b16 {%0,%1,%2,%3}, [%4];"
        : "=r"(r[0]), "=r"(r[1]), "=r"(r[2]), "=r"(r[3]) : "r"(addr));
}
__device__ __forceinline__ void mma16816(float* d, const uint32_t* a, const uint32_t* b) {
    asm volatile(
        "mma.sync.aligned.m16n8k16.row.col.f32.bf16.bf16.f32 "
        "{%0,%1,%2,%3}, {%4,%5,%6,%7}, {%8,%9}, {%0,%1,%2,%3};"
        : "+f"(d[0]), "+f"(d[1]), "+f"(d[2]), "+f"(d[3])
        : "r"(a[0]), "r"(a[1]), "r"(a[2]), "r"(a[3]), "r"(b[0]), "r"(b[1]));
}
__device__ __forceinline__ uint32_t bf2u(__nv_bfloat162 v) {
    return *reinterpret_cast<uint32_t*>(&v);
}

// ---------------------------------------------------------------------------
// Split fp32 -> (hi, lo) bf16
// ---------------------------------------------------------------------------
__global__ void split_fp32(const float* __restrict__ in,
                           __nv_bfloat16* __restrict__ hi,
                           __nv_bfloat16* __restrict__ lo, int n)
{
    int i = blockIdx.x * blockDim.x + threadIdx.x;
    if (i >= n) return;
    float v = in[i];
    __nv_bfloat16 h = __float2bfloat16(v);
    hi[i] = h;
    lo[i] = __float2bfloat16(v - __bfloat162float(h));
}

// ---------------------------------------------------------------------------
// Transpose + split: fp32 [K,N] row-major -> (hi,lo) bf16 [N,K] row-major
// ---------------------------------------------------------------------------
__global__ __launch_bounds__(256) void transpose_split(
    const float* __restrict__ in, __nv_bfloat16* __restrict__ hiT,
    __nv_bfloat16* __restrict__ loT, int K, int N)
{
    __shared__ float t[32][33];
    int n0 = blockIdx.x * 32, k0 = blockIdx.y * 32;
    int tx = threadIdx.x, ty = threadIdx.y;  // 32 x 8
#pragma unroll
    for (int i = 0; i < 32; i += 8)
        t[ty + i][tx] = in[(size_t)(k0 + ty + i) * N + n0 + tx];
    __syncthreads();
#pragma unroll
    for (int i = 0; i < 32; i += 8) {
        float v = t[tx][ty + i];
        __nv_bfloat16 h = __float2bfloat16(v);
        size_t o = (size_t)(n0 + ty + i) * K + k0 + tx;
        hiT[o] = h;
        loT[o] = __float2bfloat16(v - __bfloat162float(h));
    }
}

// ---------------------------------------------------------------------------
// GEMM core: CTA tile 256x128, warp tile 64x64 (8 warps as 4m x 2n), BK=64.
// Smem rows = 64 bf16 = 128B = 8 chunks; swizzle chunk^(row&7): conflict-free.
// K fixed at 2048. B pre-offset to its 128-row block. Split-bf16 3-product.
// Stage: Ahi 32K | Alo 32K | Bhi 16K | Blo 16K = 96KB; x2 stages = 192KB.
// ---------------------------------------------------------------------------
#define ST_ALO 32768u
#define ST_BHI 65536u
#define ST_BLO 81920u
#define QSTAGE 98304u
#define G2SMEM_BYTES 196608

__device__ __forceinline__ void gemm_core_256x128(
    uint32_t sb,
    const uint4* __restrict__ A0, const uint4* __restrict__ A1,
    const uint4* __restrict__ B0, const uint4* __restrict__ B1,
    int arow0, float D[4][8][4])
{
    const int tid = threadIdx.x, lane = tid & 31, wid = tid >> 5;
    const int m0 = (wid >> 1) * 64, n0 = (wid & 1) * 64;
    const int r_ld = tid >> 3, c_ld = tid & 7;   // 32 rows x 8 chunks per pass

    auto issue = [&](int it) {
        const uint32_t st = sb + (uint32_t)(it & 1) * QSTAGE;
        const int kc = it * 8;                   // uint4 index base (64 bf16 = 8 uint4)
#pragma unroll
        for (int g = 0; g < 8; ++g) {
            const int r = r_ld + 32 * g;
            const uint32_t d = st + (uint32_t)r * 128u
                             + ((uint32_t)(c_ld ^ (r & 7)) << 4);
            const size_t ia = (size_t)(arow0 + r) * 256 + kc + c_ld;
            cp_async16(d,          A0 + ia);
            cp_async16(d + ST_ALO, A1 + ia);
            if (g < 4) {
                const size_t ib = (size_t)r * 256 + kc + c_ld;
                cp_async16(d + ST_BHI, B0 + ib);
                cp_async16(d + ST_BLO, B1 + ib);
            }
        }
        CP_COMMIT();
    };

#pragma unroll
    for (int i = 0; i < 4; ++i)
#pragma unroll
        for (int j = 0; j < 8; ++j)
#pragma unroll
            for (int x = 0; x < 4; ++x) D[i][j][x] = 0.f;

    issue(0);

    // R5-verified lane geometry
    const int a_rowit = (lane & 7) + ((lane >> 3) & 1) * 8;
    const int a_cb    = lane >> 4;
    const int b_rowit = (lane & 7) + ((lane >> 4) << 3);
    const int b_cb    = (lane >> 3) & 1;

    const int nk = 2048 / 64;   // 32
    for (int c = 0; c < nk; ++c) {
        if (c + 1 < nk) { issue(c + 1); CP_WAIT(1); }
        else            { CP_WAIT(0); }
        __syncthreads();
        const uint32_t base = sb + (uint32_t)(c & 1) * QSTAGE;

#pragma unroll
        for (int ks = 0; ks < 4; ++ks) {
            uint32_t ah[4][4], al[4][4];
            const int acb = ks * 2 + a_cb;       // 0..7
#pragma unroll
            for (int i = 0; i < 4; ++i) {
                const int r = m0 + 16 * i + a_rowit;
                const uint32_t ad = base + (uint32_t)r * 128u
                                  + ((uint32_t)(acb ^ (r & 7)) << 4);
                ldsm4(ah[i], ad);
                ldsm4(al[i], ad + ST_ALO);
            }
            const int bcb = ks * 2 + b_cb;
#pragma unroll
            for (int jh = 0; jh < 2; ++jh) {
                uint32_t bh[2][4], bl[2][4];
#pragma unroll
                for (int j2 = 0; j2 < 2; ++j2) {
                    const int r = n0 + 16 * (2 * jh + j2) + b_rowit;
                    const uint32_t bd = base + (uint32_t)r * 128u
                                      + ((uint32_t)(bcb ^ (r & 7)) << 4);
                    ldsm4(bh[j2], bd + ST_BHI);
                    ldsm4(bl[j2], bd + ST_BLO);
                }
#pragma unroll
                for (int i = 0; i < 4; ++i)
#pragma unroll
                    for (int j2 = 0; j2 < 2; ++j2) {
                        const int j = 2 * jh + j2;
                        mma16816(D[i][2 * j],     ah[i], bh[j2]);
                        mma16816(D[i][2 * j],     ah[i], bl[j2]);
                        mma16816(D[i][2 * j],     al[i], bh[j2]);
                        mma16816(D[i][2 * j + 1], ah[i], bh[j2] + 2);
                        mma16816(D[i][2 * j + 1], ah[i], bl[j2] + 2);
                        mma16816(D[i][2 * j + 1], al[i], bh[j2] + 2);
                    }
            }
        }
        __syncthreads();
    }
}

// ---------------------------------------------------------------------------
// Fused QKV projection + RoPE + split epilogue.
// Grid: (24, Mm/256). u<16: Q head u (rope). u<20: K head u-16 (rope).
// u>=20: V head u-20 (plain split). Each col-block = exactly one head (128).
// ---------------------------------------------------------------------------
__global__ __launch_bounds__(256) void qkv_gemm(
    const uint4* __restrict__ xhi, const uint4* __restrict__ xlo,
    const uint4* __restrict__ wqh, const uint4* __restrict__ wql,
    const uint4* __restrict__ wkh, const uint4* __restrict__ wkl,
    const uint4* __restrict__ wvh, const uint4* __restrict__ wvl,
    __nv_bfloat16* __restrict__ qhi, __nv_bfloat16* __restrict__ qlo,
    __nv_bfloat16* __restrict__ khi, __nv_bfloat16* __restrict__ klo,
    __nv_bfloat16* __restrict__ vhi, __nv_bfloat16* __restrict__ vlo,
    const float* __restrict__ cs, const float* __restrict__ sn)
{
    extern __shared__ char smr[];
    const uint32_t sb = smem_u32(smr);
    const int u = blockIdx.x;
    const int arow0 = blockIdx.y * 256;

    const uint4 *B0, *B1;
    if (u < 16)      { B0 = wqh + (size_t)u * 32768;        B1 = wql + (size_t)u * 32768; }
    else if (u < 20) { B0 = wkh + (size_t)(u - 16) * 32768; B1 = wkl + (size_t)(u - 16) * 32768; }
    else             { B0 = wvh + (size_t)(u - 20) * 32768; B1 = wvl + (size_t)(u - 20) * 32768; }

    float D[4][8][4];
    gemm_core_256x128(sb, xhi, xlo, B0, B1, arow0, D);

    const int lane = threadIdx.x & 31, wid = threadIdx.x >> 5;
    const int m0 = (wid >> 1) * 64, n0 = (wid & 1) * 64;
    const int quad = lane >> 2, tq = lane & 3;

    if (u < 20) {
        __nv_bfloat16 *OH, *OL; int W, head;
        if (u < 16) { OH = qhi; OL = qlo; W = Hh * HDd;   head = u; }
        else        { OH = khi; OL = klo; W = KVHh * HDd; head = u - 16; }
#pragma unroll
        for (int i = 0; i < 4; ++i) {
            const int rr = arow0 + m0 + 16 * i + quad;
#pragma unroll
            for (int jn = 0; jn < 8; ++jn) {
                const int ir = (n0 >> 1) + 4 * jn + tq;   // rope index 0..63
#pragma unroll
                for (int hh = 0; hh < 2; ++hh) {
                    const int r = rr + 8 * hh;
                    const float x0 = D[i][jn][2 * hh];
                    const float x1 = D[i][jn][2 * hh + 1];
                    const float cv = cs[(r & (Ss - 1)) * 64 + ir];
                    const float sv = sn[(r & (Ss - 1)) * 64 + ir];
                    const float o1 = x0 * cv - x1 * sv;
                    const float o2 = x1 * cv + x0 * sv;
                    __nv_bfloat16 h1 = __float2bfloat16(o1);
                    __nv_bfloat16 h2 = __float2bfloat16(o2);
                    const size_t bs = (size_t)r * W + head * HDd;
                    OH[bs + ir]      = h1;
                    OL[bs + ir]      = __float2bfloat16(o1 - __bfloat162float(h1));
                    OH[bs + 64 + ir] = h2;
                    OL[bs + 64 + ir] = __float2bfloat16(o2 - __bfloat162float(h2));
                }
            }
        }
    } else {
        const int head = u - 20, W = KVHh * HDd;
#pragma unroll
        for (int i = 0; i < 4; ++i) {
            const int rr = arow0 + m0 + 16 * i + quad;
#pragma unroll
            for (int jn = 0; jn < 8; ++jn) {
                const int cc = head * HDd + n0 + 8 * jn + 2 * tq;
#pragma unroll
                for (int hh = 0; hh < 2; ++hh) {
                    const int r = rr + 8 * hh;
                    const float v0 = D[i][jn][2 * hh];
                    const float v1 = D[i][jn][2 * hh + 1];
                    __nv_bfloat162 h01 = __floats2bfloat162_rn(v0, v1);
                    __nv_bfloat162 l01 = __floats2bfloat162_rn(
                        v0 - __low2float(h01), v1 - __high2float(h01));
                    const size_t o = (size_t)r * W + cc;
                    *(uint32_t*)(vhi + o) = bf2u(h01);
                    *(uint32_t*)(vlo + o) = bf2u(l01);
                }
            }
        }
    }
}

// ---------------------------------------------------------------------------
// Output projection: fp32 out. Grid: (16, Mm/256).
// ---------------------------------------------------------------------------
__global__ __launch_bounds__(256) void o_gemm(
    const uint4* __restrict__ aoh, const uint4* __restrict__ aol,
    const uint4* __restrict__ woh, const uint4* __restrict__ wol,
    float* __restrict__ out)
{
    extern __shared__ char smr[];
    const uint32_t sb = smem_u32(smr);
    const int col0 = blockIdx.x * 128;
    const int arow0 = blockIdx.y * 256;

    float D[4][8][4];
    gemm_core_256x128(sb, aoh, aol,
                      woh + (size_t)col0 * 256, wol + (size_t)col0 * 256, arow0, D);

    const int lane = threadIdx.x & 31, wid = threadIdx.x >> 5;
    const int m0 = (wid >> 1) * 64, n0 = (wid & 1) * 64;
    const int quad = lane >> 2, tq = lane & 3;
#pragma unroll
    for (int i = 0; i < 4; ++i) {
        const int r = arow0 + m0 + 16 * i + quad;
#pragma unroll
        for (int jn = 0; jn < 8; ++jn) {
            const int cc = col0 + n0 + 8 * jn + 2 * tq;
            *(float2*)&out[(size_t)r * Dd + cc]       = make_float2(D[i][jn][0], D[i][jn][1]);
            *(float2*)&out[(size_t)(r + 8) * Dd + cc] = make_float2(D[i][jn][2], D[i][jn][3]);
        }
    }
}

// ---------------------------------------------------------------------------
// Flash attention on mma.sync, split-bf16 (unchanged, R7-verified).
// ---------------------------------------------------------------------------
#define ASWZ(r, c) ((uint32_t)(r) * 256u + ((uint32_t)((c) ^ ((r) & 7)) << 4))
#define ASM_QLO   32768u
#define ASM_STAGE 65536u
#define ASMEM_BYTES 196608

__global__ __launch_bounds__(256) void flash_attn_mma(
    const __nv_bfloat16* __restrict__ Qhi, const __nv_bfloat16* __restrict__ Qlo,
    const __nv_bfloat16* __restrict__ Khi, const __nv_bfloat16* __restrict__ Klo,
    const __nv_bfloat16* __restrict__ Vhi, const __nv_bfloat16* __restrict__ Vlo,
    __nv_bfloat16* __restrict__ AOhi, __nv_bfloat16* __restrict__ AOlo)
{
    extern __shared__ char sm[];
    const uint32_t sb = smem_u32(sm);
    const int tid = threadIdx.x, lane = tid & 31, wid = tid >> 5;
    const int qt = (int)gridDim.x - 1 - (int)blockIdx.x;
    const int h = blockIdx.y, b = blockIdx.z, kvh = h >> 2;
    const int q0 = qt * 128;
    const int m0 = wid * 16;
    const int nkt = 2 * qt + 2;

    const int c_ld = tid & 15, r_ld = tid >> 4;

#pragma unroll
    for (int i = 0; i < 8; ++i) {
        int r = r_ld + 16 * i;
        size_t g = ((size_t)((b * Ss + q0 + r) * Hh + h)) * HDd + c_ld * 8;
        uint32_t d = sb + ASWZ(r, c_ld);
        cp_async16(d,           Qhi + g);
        cp_async16(d + ASM_QLO, Qlo + g);
    }
    auto issue_kv = [&](int kt) {
        uint32_t st = sb + ASM_STAGE + (uint32_t)(kt & 1) * 65536u;
        int kbase = kt * 64;
#pragma unroll
        for (int i = 0; i < 4; ++i) {
            int r = r_ld + 16 * i;
            size_t g = ((size_t)((b * Ss + kbase + r) * KVHh + kvh)) * HDd + c_ld * 8;
            uint32_t d = ASWZ(r, c_ld);
            cp_async16(st + d,          Khi + g);
            cp_async16(st + 16384u + d, Klo + g);
            cp_async16(st + 32768u + d, Vhi + g);
            cp_async16(st + 49152u + d, Vlo + g);
        }
    };
    issue_kv(0);
    CP_COMMIT();

    float O[16][4];
#pragma unroll
    for (int i = 0; i < 16; ++i)
#pragma unroll
        for (int x = 0; x < 4; ++x) O[i][x] = 0.f;
    float m_lo = -1e30f, m_hi = -1e30f, l_lo = 0.f, l_hi = 0.f;

    const int quad = lane >> 2, tq = lane & 3;
    const int rit = lane & 15;
    const int chalf = lane >> 4;
    const int row_lo = q0 + m0 + quad;
    const int row_hi = row_lo + 8;
    const float scale = 0.08838834764831845f;

    for (int kt = 0; kt < nkt; ++kt) {
        if (kt + 1 < nkt) { issue_kv(kt + 1); CP_COMMIT(); CP_WAIT(1); }
        else              { CP_WAIT(0); }
        __syncthreads();

        const int kbase = kt * 64;
        if (kbase <= q0 + m0 + 15) {
            const uint32_t sK = sb + ASM_STAGE + (uint32_t)(kt & 1) * 65536u;
            const uint32_t sV = sK + 32768u;

            float S[8][4];
#pragma unroll
            for (int i = 0; i < 8; ++i)
#pragma unroll
                for (int x = 0; x < 4; ++x) S[i][x] = 0.f;

#pragma unroll
            for (int k16 = 0; k16 < 8; ++k16) {
                uint32_t qh[4], ql[4];
                uint32_t qa = sb + ASWZ(m0 + rit, k16 * 2 + chalf);
                ldsm4(qh, qa);
                ldsm4(ql, qa + ASM_QLO);
#pragma unroll
                for (int np = 0; np < 4; ++np) {
                    uint32_t kh[4], kl[4];
                    uint32_t ka = ASWZ(np * 16 + rit, k16 * 2 + chalf);
                    ldsm4(kh, sK + ka);
                    ldsm4(kl, sK + 16384u + ka);
                    uint32_t bh0[2] = {kh[0], kh[2]}, bh1[2] = {kh[1], kh[3]};
                    uint32_t bl0[2] = {kl[0], kl[2]}, bl1[2] = {kl[1], kl[3]};
                    mma16816(S[2 * np],     qh, bh0);
                    mma16816(S[2 * np],     qh, bl0);
                    mma16816(S[2 * np],     ql, bh0);
                    mma16816(S[2 * np + 1], qh, bh1);
                    mma16816(S[2 * np + 1], qh, bl1);
                    mma16816(S[2 * np + 1], ql, bh1);
                }
            }

            const bool do_mask = (kt >= nkt - 2);
            float tmx_lo = -1e30f, tmx_hi = -1e30f;
#pragma unroll
            for (int nb = 0; nb < 8; ++nb) {
                int c0 = kbase + nb * 8 + tq * 2;
                float v0 = S[nb][0] * scale, v1 = S[nb][1] * scale;
                float v2 = S[nb][2] * scale, v3 = S[nb][3] * scale;
                if (do_mask) {
                    if (c0     > row_lo) v0 = -1e30f;
                    if (c0 + 1 > row_lo) v1 = -1e30f;
                    if (c0     > row_hi) v2 = -1e30f;
                    if (c0 + 1 > row_hi) v3 = -1e30f;
                }
                S[nb][0] = v0; S[nb][1] = v1; S[nb][2] = v2; S[nb][3] = v3;
                tmx_lo = fmaxf(tmx_lo, fmaxf(v0, v1));
                tmx_hi = fmaxf(tmx_hi, fmaxf(v2, v3));
            }
            tmx_lo = fmaxf(tmx_lo, __shfl_xor_sync(0xffffffffu, tmx_lo, 1));
            tmx_lo = fmaxf(tmx_lo, __shfl_xor_sync(0xffffffffu, tmx_lo, 2));
            tmx_hi = fmaxf(tmx_hi, __shfl_xor_sync(0xffffffffu, tmx_hi, 1));
            tmx_hi = fmaxf(tmx_hi, __shfl_xor_sync(0xffffffffu, tmx_hi, 2));
            float mn_lo = fmaxf(m_lo, tmx_lo), mn_hi = fmaxf(m_hi, tmx_hi);
            float a_lo = __expf(m_lo - mn_lo), a_hi = __expf(m_hi - mn_hi);
            m_lo = mn_lo; m_hi = mn_hi;
            float s_lo = 0.f, s_hi = 0.f;
#pragma unroll
            for (int nb = 0; nb < 8; ++nb) {
                S[nb][0] = __expf(S[nb][0] - mn_lo);
                S[nb][1] = __expf(S[nb][1] - mn_lo);
                S[nb][2] = __expf(S[nb][2] - mn_hi);
                S[nb][3] = __expf(S[nb][3] - mn_hi);
                s_lo += S[nb][0] + S[nb][1];
                s_hi += S[nb][2] + S[nb][3];
            }
            s_lo += __shfl_xor_sync(0xffffffffu, s_lo, 1);
            s_lo += __shfl_xor_sync(0xffffffffu, s_lo, 2);
            s_hi += __shfl_xor_sync(0xffffffffu, s_hi, 1);
            s_hi += __shfl_xor_sync(0xffffffffu, s_hi, 2);
            l_lo = l_lo * a_lo + s_lo;
            l_hi = l_hi * a_hi + s_hi;
#pragma unroll
            for (int nb = 0; nb < 16; ++nb) {
                O[nb][0] *= a_lo; O[nb][1] *= a_lo;
                O[nb][2] *= a_hi; O[nb][3] *= a_hi;
            }

            uint32_t ph[4][4], pl[4][4];
#pragma unroll
            for (int kb = 0; kb < 4; ++kb) {
#pragma unroll
                for (int hf = 0; hf < 2; ++hf) {
                    int nb = 2 * kb + hf;
                    __nv_bfloat162 h01 = __floats2bfloat162_rn(S[nb][0], S[nb][1]);
                    __nv_bfloat162 h23 = __floats2bfloat162_rn(S[nb][2], S[nb][3]);
                    __nv_bfloat162 l01 = __floats2bfloat162_rn(
                        S[nb][0] - __low2float(h01), S[nb][1] - __high2float(h01));
                    __nv_bfloat162 l23 = __floats2bfloat162_rn(
                        S[nb][2] - __low2float(h23), S[nb][3] - __high2float(h23));
                    ph[kb][2 * hf]     = bf2u(h01);
                    ph[kb][2 * hf + 1] = bf2u(h23);
                    pl[kb][2 * hf]     = bf2u(l01);
                    pl[kb][2 * hf + 1] = bf2u(l23);
                }
            }

#pragma unroll
            for (int kb = 0; kb < 4; ++kb) {
#pragma unroll
                for (int np2 = 0; np2 < 8; ++np2) {
                    uint32_t vh[4], vl[4];
                    uint32_t va = ASWZ(kb * 16 + rit, np2 * 2 + chalf);
                    ldsm4t(vh, sV + va);
                    ldsm4t(vl, sV + 16384u + va);
                    uint32_t bh0[2] = {vh[0], vh[1]}, bh1[2] = {vh[2], vh[3]};
                    uint32_t bl0[2] = {vl[0], vl[1]}, bl1[2] = {vl[2], vl[3]};
                    mma16816(O[2 * np2],     ph[kb], bh0);
                    mma16816(O[2 * np2],     ph[kb], bl0);
                    mma16816(O[2 * np2],     pl[kb], bh0);
                    mma16816(O[2 * np2 + 1], ph[kb], bh1);
                    mma16816(O[2 * np2 + 1], ph[kb], bl1);
                    mma16816(O[2 * np2 + 1], pl[kb], bh1);
                }
            }
        }
        __syncthreads();
    }

    float i_lo = 1.f / l_lo, i_hi = 1.f / l_hi;
#pragma unroll
    for (int nb = 0; nb < 16; ++nb) {
        float v0 = O[nb][0] * i_lo, v1 = O[nb][1] * i_lo;
        float v2 = O[nb][2] * i_hi, v3 = O[nb][3] * i_hi;
        size_t o_lo = (size_t)(b * Ss + row_lo) * Dd + h * HDd + nb * 8 + tq * 2;
        size_t o_hi = o_lo + 8 * (size_t)Dd;
        __nv_bfloat162 h01 = __floats2bfloat162_rn(v0, v1);
        __nv_bfloat162 l01 = __floats2bfloat162_rn(v0 - __low2float(h01), v1 - __high2float(h01));
        __nv_bfloat162 h23 = __floats2bfloat162_rn(v2, v3);
        __nv_bfloat162 l23 = __floats2bfloat162_rn(v2 - __low2float(h23), v3 - __high2float(h23));
        *(uint32_t*)(AOhi + o_lo) = bf2u(h01);
        *(uint32_t*)(AOlo + o_lo) = bf2u(l01);
        *(uint32_t*)(AOhi + o_hi) = bf2u(h23);
        *(uint32_t*)(AOlo + o_hi) = bf2u(l23);
    }
}

// ---------------------------------------------------------------------------
// Launch. Inputs: hidden_states, attention_mask, cos, sin, Wq, Wk, Wv, Wo
// ---------------------------------------------------------------------------
extern "C" void kernel_launch(void* const* d_in, const int* in_sizes, int n_in,
                              void* d_out, int out_size)
{
    const float* X  = (const float*)d_in[0];
    const float* cs = (const float*)d_in[2];
    const float* sn = (const float*)d_in[3];
    const float* Wq = (const float*)d_in[4];
    const float* Wk = (const float*)d_in[5];
    const float* Wv = (const float*)d_in[6];
    const float* Wo = (const float*)d_in[7];
    float* out = (float*)d_out;

    __nv_bfloat16 *xhi, *xlo, *wqh, *wql, *wkh, *wkl, *wvh, *wvl, *woh, *wol;
    __nv_bfloat16 *qhi, *qlo, *khi, *klo, *vhi, *vlo, *aoh, *aol;
    cudaGetSymbolAddress((void**)&xhi, g_xhi);
    cudaGetSymbolAddress((void**)&xlo, g_xlo);
    cudaGetSymbolAddress((void**)&wqh, g_wqt_hi);
    cudaGetSymbolAddress((void**)&wql, g_wqt_lo);
    cudaGetSymbolAddress((void**)&wkh, g_wkt_hi);
    cudaGetSymbolAddress((void**)&wkl, g_wkt_lo);
    cudaGetSymbolAddress((void**)&wvh, g_wvt_hi);
    cudaGetSymbolAddress((void**)&wvl, g_wvt_lo);
    cudaGetSymbolAddress((void**)&woh, g_wot_hi);
    cudaGetSymbolAddress((void**)&wol, g_wot_lo);
    cudaGetSymbolAddress((void**)&qhi, g_qhi);
    cudaGetSymbolAddress((void**)&qlo, g_qlo);
    cudaGetSymbolAddress((void**)&khi, g_khi);
    cudaGetSymbolAddress((void**)&klo, g_klo);
    cudaGetSymbolAddress((void**)&vhi, g_vhi);
    cudaGetSymbolAddress((void**)&vlo, g_vlo);
    cudaGetSymbolAddress((void**)&aoh, g_aohi);
    cudaGetSymbolAddress((void**)&aol, g_aolo);

    cudaFuncSetAttribute(qkv_gemm, cudaFuncAttributeMaxDynamicSharedMemorySize, G2SMEM_BYTES);
    cudaFuncSetAttribute(o_gemm,   cudaFuncAttributeMaxDynamicSharedMemorySize, G2SMEM_BYTES);
    cudaFuncSetAttribute(flash_attn_mma, cudaFuncAttributeMaxDynamicSharedMemorySize, ASMEM_BYTES);

    // Weight transpose+split and input split
    {
        dim3 blk(32, 8);
        transpose_split<<<dim3(Dd / 32, Dd / 32), blk>>>(Wq, wqh, wql, Dd, Dd);
        transpose_split<<<dim3((KVHh * HDd) / 32, Dd / 32), blk>>>(Wk, wkh, wkl, Dd, KVHh * HDd);
        transpose_split<<<dim3((KVHh * HDd) / 32, Dd / 32), blk>>>(Wv, wvh, wvl, Dd, KVHh * HDd);
        transpose_split<<<dim3(Dd / 32, Dd / 32), blk>>>(Wo, woh, wol, Hh * HDd, Dd);
        int nx = Mm * Dd;
        split_fp32<<<(nx + 255) / 256, 256>>>(X, xhi, xlo, nx);
    }

    // Fused QKV projection (+RoPE for Q/K, split outputs)
    qkv_gemm<<<dim3(24, Mm / 256), 256, G2SMEM_BYTES>>>(
        (const uint4*)xhi, (const uint4*)xlo,
        (const uint4*)wqh, (const uint4*)wql,
        (const uint4*)wkh, (const uint4*)wkl,
        (const uint4*)wvh, (const uint4*)wvl,
        qhi, qlo, khi, klo, vhi, vlo, cs, sn);

    // Attention (tensor-core, split bf16), writes split AO directly
    flash_attn_mma<<<dim3(Ss / 128, Hh, Bb), 256, ASMEM_BYTES>>>(
        qhi, qlo, khi, klo, vhi, vlo, aoh, aol);

    // Output projection -> fp32 out
    o_gemm<<<dim3(Dd / 128, Mm / 256), 256, G2SMEM_BYTES>>>(
        (const uint4*)aoh, (const uint4*)aol,
        (const uint4*)woh, (const uint4*)wol, out);
}

// round 13
// speedup vs baseline: 4.0959x; 1.1712x over previous
#include <cuda_runtime.h>
#include <cuda_bf16.h>
#include <cuda_fp16.h>
#include <math.h>
#include <stdint.h>

// Problem constants
#define Bb   2
#define Ss   2048
#define Dd   2048
#define Hh   16
#define KVHh 4
#define HDd  128
#define Mm   (Bb * Ss)   // 4096

// ---------------------------------------------------------------------------
// Scratch (device globals). 16B-aligned (vector access).
// ---------------------------------------------------------------------------
__device__ __align__(16) __nv_bfloat16 g_xhi[(size_t)Mm * Dd];
__device__ __align__(16) __nv_bfloat16 g_xlo[(size_t)Mm * Dd];
__device__ __align__(16) __nv_bfloat16 g_wqt_hi[(size_t)Dd * Dd];
__device__ __align__(16) __nv_bfloat16 g_wqt_lo[(size_t)Dd * Dd];
__device__ __align__(16) __nv_bfloat16 g_wkt_hi[(size_t)(KVHh*HDd) * Dd];
__device__ __align__(16) __nv_bfloat16 g_wkt_lo[(size_t)(KVHh*HDd) * Dd];
__device__ __align__(16) __nv_bfloat16 g_wvt_hi[(size_t)(KVHh*HDd) * Dd];
__device__ __align__(16) __nv_bfloat16 g_wvt_lo[(size_t)(KVHh*HDd) * Dd];
__device__ __align__(16) __half        g_wot16[(size_t)Dd * Dd];    // Wo^T fp16

__device__ __align__(16) __nv_bfloat16 g_qhi[(size_t)Mm * Hh   * HDd];
__device__ __align__(16) __nv_bfloat16 g_qlo[(size_t)Mm * Hh   * HDd];
__device__ __align__(16) __nv_bfloat16 g_khi[(size_t)Mm * KVHh * HDd];
__device__ __align__(16) __nv_bfloat16 g_klo[(size_t)Mm * KVHh * HDd];
__device__ __align__(16) __nv_bfloat16 g_vhi[(size_t)Mm * KVHh * HDd];
__device__ __align__(16) __nv_bfloat16 g_vlo[(size_t)Mm * KVHh * HDd];
__device__ __align__(16) __half        g_ao16[(size_t)Mm * Dd];     // attention out fp16

// ---------------------------------------------------------------------------
// Helpers (plain PTX, nothing sm_103a-gated)
// ---------------------------------------------------------------------------
__device__ __forceinline__ uint32_t smem_u32(const void* p) {
    uint32_t a;
    asm("{ .reg .u64 t; cvta.to.shared.u64 t, %1; cvt.u32.u64 %0, t; }"
        : "=r"(a) : "l"(p));
    return a;
}
__device__ __forceinline__ void cp_async16(uint32_t dst, const void* src) {
    asm volatile("cp.async.cg.shared.global [%0], [%1], 16;" :: "r"(dst), "l"(src));
}
#define CP_COMMIT()  asm volatile("cp.async.commit_group;" ::: "memory")
#define CP_WAIT(n)   asm volatile("cp.async.wait_group %0;" :: "n"(n) : "memory")

__device__ __forceinline__ void ldsm4(uint32_t* r, uint32_t addr) {
    asm volatile("ldmatrix.sync.aligned.m8n8.x4.shared.b16 {%0,%1,%2,%3}, [%4];"
        : "=r"(r[0]), "=r"(r[1]), "=r"(r[2]), "=r"(r[3]) : "r"(addr));
}
__device__ __forceinline__ void ldsm4t(uint32_t* r, uint32_t addr) {
    asm volatile("ldmatrix.sync.aligned.m8n8.x4.trans.shared.b16 {%0,%1,%2,%3}, [%4];"
        : "=r"(r[0]), "=r"(r[1]), "=r"(r[2]), "=r"(r[3]) : "r"(addr));
}
__device__ __forceinline__ void mma16816(float* d, const uint32_t* a, const uint32_t* b) {
    asm volatile(
        "mma.sync.aligned.m16n8k16.row.col.f32.bf16.bf16.f32 "
        "{%0,%1,%2,%3}, {%4,%5,%6,%7}, {%8,%9}, {%0,%1,%2,%3};"
        : "+f"(d[0]), "+f"(d[1]), "+f"(d[2]), "+f"(d[3])
        : "r"(a[0]), "r"(a[1]), "r"(a[2]), "r"(a[3]), "r"(b[0]), "r"(b[1]));
}
__device__ __forceinline__ void mma16816h(float* d, const uint32_t* a, const uint32_t* b) {
    asm volatile(
        "mma.sync.aligned.m16n8k16.row.col.f32.f16.f16.f32 "
        "{%0,%1,%2,%3}, {%4,%5,%6,%7}, {%8,%9}, {%0,%1,%2,%3};"
        : "+f"(d[0]), "+f"(d[1]), "+f"(d[2]), "+f"(d[3])
        : "r"(a[0]), "r"(a[1]), "r"(a[2]), "r"(a[3]), "r"(b[0]), "r"(b[1]));
}
__device__ __forceinline__ uint32_t bf2u(__nv_bfloat162 v) {
    return *reinterpret_cast<uint32_t*>(&v);
}

// ---------------------------------------------------------------------------
// Split fp32 -> (hi, lo) bf16  (X input)
// ---------------------------------------------------------------------------
__global__ void split_fp32(const float* __restrict__ in,
                           __nv_bfloat16* __restrict__ hi,
                           __nv_bfloat16* __restrict__ lo, int n)
{
    int i = blockIdx.x * blockDim.x + threadIdx.x;
    if (i >= n) return;
    float v = in[i];
    __nv_bfloat16 h = __float2bfloat16(v);
    hi[i] = h;
    lo[i] = __float2bfloat16(v - __bfloat162float(h));
}

// ---------------------------------------------------------------------------
// Fused weight transpose: all 4 weights in one launch.
// Wq/Wk/Wv -> split-bf16 [N,K]; Wo -> fp16 single [N,K]. K (src rows) = 2048.
// Flattened block ids: Wq 0..4095 | Wk 4096..5119 | Wv 5120..6143 | Wo 6144..10239
// ---------------------------------------------------------------------------
__global__ __launch_bounds__(256) void transpose_all(
    const float* __restrict__ Wq, const float* __restrict__ Wk,
    const float* __restrict__ Wv, const float* __restrict__ Wo)
{
    __shared__ float t[32][33];
    int b = blockIdx.x;
    const float* in;
    __nv_bfloat16 *hiT = nullptr, *loT = nullptr;
    __half* h16 = nullptr;
    int N, nb, kb;
    if (b < 4096)      { in = Wq; hiT = g_wqt_hi; loT = g_wqt_lo; N = 2048; nb = b & 63; kb = b >> 6; }
    else if (b < 5120) { b -= 4096; in = Wk; hiT = g_wkt_hi; loT = g_wkt_lo; N = 512; nb = b & 15; kb = b >> 4; }
    else if (b < 6144) { b -= 5120; in = Wv; hiT = g_wvt_hi; loT = g_wvt_lo; N = 512; nb = b & 15; kb = b >> 4; }
    else               { b -= 6144; in = Wo; h16 = g_wot16; N = 2048; nb = b & 63; kb = b >> 6; }

    int n0 = nb * 32, k0 = kb * 32;
    int tx = threadIdx.x, ty = threadIdx.y;  // 32 x 8
#pragma unroll
    for (int i = 0; i < 32; i += 8)
        t[ty + i][tx] = in[(size_t)(k0 + ty + i) * N + n0 + tx];
    __syncthreads();
#pragma unroll
    for (int i = 0; i < 32; i += 8) {
        float v = t[tx][ty + i];
        size_t o = (size_t)(n0 + ty + i) * 2048 + k0 + tx;
        if (h16) {
            h16[o] = __float2half(v);
        } else {
            __nv_bfloat16 h = __float2bfloat16(v);
            hiT[o] = h;
            loT[o] = __float2bfloat16(v - __bfloat162float(h));
        }
    }
}

// ---------------------------------------------------------------------------
// GEMM core (split-bf16 3-product): CTA 256x128, warp 64x64, BK=64, 2 stages.
// Smem rows 128B, swizzle chunk^(row&7) -> conflict-free ldmatrix.
// ---------------------------------------------------------------------------
#define ST_ALO 32768u
#define ST_BHI 65536u
#define ST_BLO 81920u
#define QSTAGE 98304u
#define G2SMEM_BYTES 196608

__device__ __forceinline__ void gemm_core_256x128(
    uint32_t sb,
    const uint4* __restrict__ A0, const uint4* __restrict__ A1,
    const uint4* __restrict__ B0, const uint4* __restrict__ B1,
    int arow0, float D[4][8][4])
{
    const int tid = threadIdx.x, lane = tid & 31, wid = tid >> 5;
    const int m0 = (wid >> 1) * 64, n0 = (wid & 1) * 64;
    const int r_ld = tid >> 3, c_ld = tid & 7;

    auto issue = [&](int it) {
        const uint32_t st = sb + (uint32_t)(it & 1) * QSTAGE;
        const int kc = it * 8;
#pragma unroll
        for (int g = 0; g < 8; ++g) {
            const int r = r_ld + 32 * g;
            const uint32_t d = st + (uint32_t)r * 128u
                             + ((uint32_t)(c_ld ^ (r & 7)) << 4);
            const size_t ia = (size_t)(arow0 + r) * 256 + kc + c_ld;
            cp_async16(d,          A0 + ia);
            cp_async16(d + ST_ALO, A1 + ia);
            if (g < 4) {
                const size_t ib = (size_t)r * 256 + kc + c_ld;
                cp_async16(d + ST_BHI, B0 + ib);
                cp_async16(d + ST_BLO, B1 + ib);
            }
        }
        CP_COMMIT();
    };

#pragma unroll
    for (int i = 0; i < 4; ++i)
#pragma unroll
        for (int j = 0; j < 8; ++j)
#pragma unroll
            for (int x = 0; x < 4; ++x) D[i][j][x] = 0.f;

    issue(0);

    const int a_rowit = (lane & 7) + ((lane >> 3) & 1) * 8;
    const int a_cb    = lane >> 4;
    const int b_rowit = (lane & 7) + ((lane >> 4) << 3);
    const int b_cb    = (lane >> 3) & 1;

    const int nk = 2048 / 64;
    for (int c = 0; c < nk; ++c) {
        if (c + 1 < nk) { issue(c + 1); CP_WAIT(1); }
        else            { CP_WAIT(0); }
        __syncthreads();
        const uint32_t base = sb + (uint32_t)(c & 1) * QSTAGE;

#pragma unroll
        for (int ks = 0; ks < 4; ++ks) {
            uint32_t ah[4][4], al[4][4];
            const int acb = ks * 2 + a_cb;
#pragma unroll
            for (int i = 0; i < 4; ++i) {
                const int r = m0 + 16 * i + a_rowit;
                const uint32_t ad = base + (uint32_t)r * 128u
                                  + ((uint32_t)(acb ^ (r & 7)) << 4);
                ldsm4(ah[i], ad);
                ldsm4(al[i], ad + ST_ALO);
            }
            const int bcb = ks * 2 + b_cb;
#pragma unroll
            for (int jh = 0; jh < 2; ++jh) {
                uint32_t bh[2][4], bl[2][4];
#pragma unroll
                for (int j2 = 0; j2 < 2; ++j2) {
                    const int r = n0 + 16 * (2 * jh + j2) + b_rowit;
                    const uint32_t bd = base + (uint32_t)r * 128u
                                      + ((uint32_t)(bcb ^ (r & 7)) << 4);
                    ldsm4(bh[j2], bd + ST_BHI);
                    ldsm4(bl[j2], bd + ST_BLO);
                }
#pragma unroll
                for (int i = 0; i < 4; ++i)
#pragma unroll
                    for (int j2 = 0; j2 < 2; ++j2) {
                        const int j = 2 * jh + j2;
                        mma16816(D[i][2 * j],     ah[i], bh[j2]);
                        mma16816(D[i][2 * j],     ah[i], bl[j2]);
                        mma16816(D[i][2 * j],     al[i], bh[j2]);
                        mma16816(D[i][2 * j + 1], ah[i], bh[j2] + 2);
                        mma16816(D[i][2 * j + 1], ah[i], bl[j2] + 2);
                        mma16816(D[i][2 * j + 1], al[i], bh[j2] + 2);
                    }
            }
        }
        __syncthreads();
    }
}

// ---------------------------------------------------------------------------
// Fused QKV projection + RoPE + split epilogue.
// Grid: (24, Mm/256). u<16: Q head u (rope). u<20: K head u-16 (rope).
// u>=20: V head u-20 (plain split).
// ---------------------------------------------------------------------------
__global__ __launch_bounds__(256) void qkv_gemm(
    const uint4* __restrict__ xhi, const uint4* __restrict__ xlo,
    const uint4* __restrict__ wqh, const uint4* __restrict__ wql,
    const uint4* __restrict__ wkh, const uint4* __restrict__ wkl,
    const uint4* __restrict__ wvh, const uint4* __restrict__ wvl,
    __nv_bfloat16* __restrict__ qhi, __nv_bfloat16* __restrict__ qlo,
    __nv_bfloat16* __restrict__ khi, __nv_bfloat16* __restrict__ klo,
    __nv_bfloat16* __restrict__ vhi, __nv_bfloat16* __restrict__ vlo,
    const float* __restrict__ cs, const float* __restrict__ sn)
{
    extern __shared__ char smr[];
    const uint32_t sb = smem_u32(smr);
    const int u = blockIdx.x;
    const int arow0 = blockIdx.y * 256;

    const uint4 *B0, *B1;
    if (u < 16)      { B0 = wqh + (size_t)u * 32768;        B1 = wql + (size_t)u * 32768; }
    else if (u < 20) { B0 = wkh + (size_t)(u - 16) * 32768; B1 = wkl + (size_t)(u - 16) * 32768; }
    else             { B0 = wvh + (size_t)(u - 20) * 32768; B1 = wvl + (size_t)(u - 20) * 32768; }

    float D[4][8][4];
    gemm_core_256x128(sb, xhi, xlo, B0, B1, arow0, D);

    const int lane = threadIdx.x & 31, wid = threadIdx.x >> 5;
    const int m0 = (wid >> 1) * 64, n0 = (wid & 1) * 64;
    const int quad = lane >> 2, tq = lane & 3;

    if (u < 20) {
        __nv_bfloat16 *OH, *OL; int W, head;
        if (u < 16) { OH = qhi; OL = qlo; W = Hh * HDd;   head = u; }
        else        { OH = khi; OL = klo; W = KVHh * HDd; head = u - 16; }
#pragma unroll
        for (int i = 0; i < 4; ++i) {
            const int rr = arow0 + m0 + 16 * i + quad;
#pragma unroll
            for (int jn = 0; jn < 8; ++jn) {
                const int ir = (n0 >> 1) + 4 * jn + tq;
#pragma unroll
                for (int hh = 0; hh < 2; ++hh) {
                    const int r = rr + 8 * hh;
                    const float x0 = D[i][jn][2 * hh];
                    const float x1 = D[i][jn][2 * hh + 1];
                    const float cv = cs[(r & (Ss - 1)) * 64 + ir];
                    const float sv = sn[(r & (Ss - 1)) * 64 + ir];
                    const float o1 = x0 * cv - x1 * sv;
                    const float o2 = x1 * cv + x0 * sv;
                    __nv_bfloat16 h1 = __float2bfloat16(o1);
                    __nv_bfloat16 h2 = __float2bfloat16(o2);
                    const size_t bs = (size_t)r * W + head * HDd;
                    OH[bs + ir]      = h1;
                    OL[bs + ir]      = __float2bfloat16(o1 - __bfloat162float(h1));
                    OH[bs + 64 + ir] = h2;
                    OL[bs + 64 + ir] = __float2bfloat16(o2 - __bfloat162float(h2));
                }
            }
        }
    } else {
        const int head = u - 20, W = KVHh * HDd;
#pragma unroll
        for (int i = 0; i < 4; ++i) {
            const int rr = arow0 + m0 + 16 * i + quad;
#pragma unroll
            for (int jn = 0; jn < 8; ++jn) {
                const int cc = head * HDd + n0 + 8 * jn + 2 * tq;
#pragma unroll
                for (int hh = 0; hh < 2; ++hh) {
                    const int r = rr + 8 * hh;
                    const float v0 = D[i][jn][2 * hh];
                    const float v1 = D[i][jn][2 * hh + 1];
                    __nv_bfloat162 h01 = __floats2bfloat162_rn(v0, v1);
                    __nv_bfloat162 l01 = __floats2bfloat162_rn(
                        v0 - __low2float(h01), v1 - __high2float(h01));
                    const size_t o = (size_t)r * W + cc;
                    *(uint32_t*)(vhi + o) = bf2u(h01);
                    *(uint32_t*)(vlo + o) = bf2u(l01);
                }
            }
        }
    }
}

// ---------------------------------------------------------------------------
// Output projection, fp16 single-product: CTA 256x128, warp 64x64, BK=64,
// 2 stages of 48KB (A 32K | B 16K). Same conflict-free swizzle/geometry.
// ---------------------------------------------------------------------------
#define HSTG_B 32768u
#define HSTAGE 49152u
#define H_SMEM_BYTES 98304

__global__ __launch_bounds__(256) void o_gemm16(
    const uint4* __restrict__ A0, const uint4* __restrict__ W0,
    float* __restrict__ out)
{
    extern __shared__ char smr[];
    const uint32_t sb = smem_u32(smr);
    const int tid = threadIdx.x, lane = tid & 31, wid = tid >> 5;
    const int col0 = blockIdx.x * 128;
    const int arow0 = blockIdx.y * 256;
    const uint4* B0 = W0 + (size_t)col0 * 256;

    const int m0 = (wid >> 1) * 64, n0 = (wid & 1) * 64;
    const int r_ld = tid >> 3, c_ld = tid & 7;

    auto issue = [&](int it) {
        const uint32_t st = sb + (uint32_t)(it & 1) * HSTAGE;
        const int kc = it * 8;
#pragma unroll
        for (int g = 0; g < 8; ++g) {
            const int r = r_ld + 32 * g;
            const uint32_t d = st + (uint32_t)r * 128u
                             + ((uint32_t)(c_ld ^ (r & 7)) << 4);
            cp_async16(d, A0 + (size_t)(arow0 + r) * 256 + kc + c_ld);
            if (g < 4)
                cp_async16(d + HSTG_B, B0 + (size_t)r * 256 + kc + c_ld);
        }
        CP_COMMIT();
    };

    float D[4][8][4];
#pragma unroll
    for (int i = 0; i < 4; ++i)
#pragma unroll
        for (int j = 0; j < 8; ++j)
#pragma unroll
            for (int x = 0; x < 4; ++x) D[i][j][x] = 0.f;

    issue(0);

    const int a_rowit = (lane & 7) + ((lane >> 3) & 1) * 8;
    const int a_cb    = lane >> 4;
    const int b_rowit = (lane & 7) + ((lane >> 4) << 3);
    const int b_cb    = (lane >> 3) & 1;

    const int nk = 2048 / 64;
    for (int c = 0; c < nk; ++c) {
        if (c + 1 < nk) { issue(c + 1); CP_WAIT(1); }
        else            { CP_WAIT(0); }
        __syncthreads();
        const uint32_t base = sb + (uint32_t)(c & 1) * HSTAGE;

#pragma unroll
        for (int ks = 0; ks < 4; ++ks) {
            uint32_t ah[4][4];
            const int acb = ks * 2 + a_cb;
#pragma unroll
            for (int i = 0; i < 4; ++i) {
                const int r = m0 + 16 * i + a_rowit;
                ldsm4(ah[i], base + (uint32_t)r * 128u
                             + ((uint32_t)(acb ^ (r & 7)) << 4));
            }
            const int bcb = ks * 2 + b_cb;
#pragma unroll
            for (int jh = 0; jh < 2; ++jh) {
                uint32_t bh[2][4];
#pragma unroll
                for (int j2 = 0; j2 < 2; ++j2) {
                    const int r = n0 + 16 * (2 * jh + j2) + b_rowit;
                    ldsm4(bh[j2], base + HSTG_B + (uint32_t)r * 128u
                                  + ((uint32_t)(bcb ^ (r & 7)) << 4));
                }
#pragma unroll
                for (int i = 0; i < 4; ++i)
#pragma unroll
                    for (int j2 = 0; j2 < 2; ++j2) {
                        const int j = 2 * jh + j2;
                        mma16816h(D[i][2 * j],     ah[i], bh[j2]);
                        mma16816h(D[i][2 * j + 1], ah[i], bh[j2] + 2);
                    }
            }
        }
        __syncthreads();
    }

    const int quad = lane >> 2, tq = lane & 3;
#pragma unroll
    for (int i = 0; i < 4; ++i) {
        const int r = arow0 + m0 + 16 * i + quad;
#pragma unroll
        for (int jn = 0; jn < 8; ++jn) {
            const int cc = col0 + n0 + 8 * jn + 2 * tq;
            *(float2*)&out[(size_t)r * Dd + cc]       = make_float2(D[i][jn][0], D[i][jn][1]);
            *(float2*)&out[(size_t)(r + 8) * Dd + cc] = make_float2(D[i][jn][2], D[i][jn][3]);
        }
    }
}

// ---------------------------------------------------------------------------
// Flash attention on mma.sync, split-bf16 (R7-verified). Epilogue writes
// fp16 AO single (feeds o_gemm16).
// ---------------------------------------------------------------------------
#define ASWZ(r, c) ((uint32_t)(r) * 256u + ((uint32_t)((c) ^ ((r) & 7)) << 4))
#define ASM_QLO   32768u
#define ASM_STAGE 65536u
#define ASMEM_BYTES 196608

__global__ __launch_bounds__(256) void flash_attn_mma(
    const __nv_bfloat16* __restrict__ Qhi, const __nv_bfloat16* __restrict__ Qlo,
    const __nv_bfloat16* __restrict__ Khi, const __nv_bfloat16* __restrict__ Klo,
    const __nv_bfloat16* __restrict__ Vhi, const __nv_bfloat16* __restrict__ Vlo,
    __half* __restrict__ AO16)
{
    extern __shared__ char sm[];
    const uint32_t sb = smem_u32(sm);
    const int tid = threadIdx.x, lane = tid & 31, wid = tid >> 5;
    const int qt = (int)gridDim.x - 1 - (int)blockIdx.x;
    const int h = blockIdx.y, b = blockIdx.z, kvh = h >> 2;
    const int q0 = qt * 128;
    const int m0 = wid * 16;
    const int nkt = 2 * qt + 2;

    const int c_ld = tid & 15, r_ld = tid >> 4;

#pragma unroll
    for (int i = 0; i < 8; ++i) {
        int r = r_ld + 16 * i;
        size_t g = ((size_t)((b * Ss + q0 + r) * Hh + h)) * HDd + c_ld * 8;
        uint32_t d = sb + ASWZ(r, c_ld);
        cp_async16(d,           Qhi + g);
        cp_async16(d + ASM_QLO, Qlo + g);
    }
    auto issue_kv = [&](int kt) {
        uint32_t st = sb + ASM_STAGE + (uint32_t)(kt & 1) * 65536u;
        int kbase = kt * 64;
#pragma unroll
        for (int i = 0; i < 4; ++i) {
            int r = r_ld + 16 * i;
            size_t g = ((size_t)((b * Ss + kbase + r) * KVHh + kvh)) * HDd + c_ld * 8;
            uint32_t d = ASWZ(r, c_ld);
            cp_async16(st + d,          Khi + g);
            cp_async16(st + 16384u + d, Klo + g);
            cp_async16(st + 32768u + d, Vhi + g);
            cp_async16(st + 49152u + d, Vlo + g);
        }
    };
    issue_kv(0);
    CP_COMMIT();

    float O[16][4];
#pragma unroll
    for (int i = 0; i < 16; ++i)
#pragma unroll
        for (int x = 0; x < 4; ++x) O[i][x] = 0.f;
    float m_lo = -1e30f, m_hi = -1e30f, l_lo = 0.f, l_hi = 0.f;

    const int quad = lane >> 2, tq = lane & 3;
    const int rit = lane & 15;
    const int chalf = lane >> 4;
    const int row_lo = q0 + m0 + quad;
    const int row_hi = row_lo + 8;
    const float scale = 0.08838834764831845f;

    for (int kt = 0; kt < nkt; ++kt) {
        if (kt + 1 < nkt) { issue_kv(kt + 1); CP_COMMIT(); CP_WAIT(1); }
        else              { CP_WAIT(0); }
        __syncthreads();

        const int kbase = kt * 64;
        if (kbase <= q0 + m0 + 15) {
            const uint32_t sK = sb + ASM_STAGE + (uint32_t)(kt & 1) * 65536u;
            const uint32_t sV = sK + 32768u;

            float S[8][4];
#pragma unroll
            for (int i = 0; i < 8; ++i)
#pragma unroll
                for (int x = 0; x < 4; ++x) S[i][x] = 0.f;

#pragma unroll
            for (int k16 = 0; k16 < 8; ++k16) {
                uint32_t qh[4], ql[4];
                uint32_t qa = sb + ASWZ(m0 + rit, k16 * 2 + chalf);
                ldsm4(qh, qa);
                ldsm4(ql, qa + ASM_QLO);
#pragma unroll
                for (int np = 0; np < 4; ++np) {
                    uint32_t kh[4], kl[4];
                    uint32_t ka = ASWZ(np * 16 + rit, k16 * 2 + chalf);
                    ldsm4(kh, sK + ka);
                    ldsm4(kl, sK + 16384u + ka);
                    uint32_t bh0[2] = {kh[0], kh[2]}, bh1[2] = {kh[1], kh[3]};
                    uint32_t bl0[2] = {kl[0], kl[2]}, bl1[2] = {kl[1], kl[3]};
                    mma16816(S[2 * np],     qh, bh0);
                    mma16816(S[2 * np],     qh, bl0);
                    mma16816(S[2 * np],     ql, bh0);
                    mma16816(S[2 * np + 1], qh, bh1);
                    mma16816(S[2 * np + 1], qh, bl1);
                    mma16816(S[2 * np + 1], ql, bh1);
                }
            }

            const bool do_mask = (kt >= nkt - 2);
            float tmx_lo = -1e30f, tmx_hi = -1e30f;
#pragma unroll
            for (int nb = 0; nb < 8; ++nb) {
                int c0 = kbase + nb * 8 + tq * 2;
                float v0 = S[nb][0] * scale, v1 = S[nb][1] * scale;
                float v2 = S[nb][2] * scale, v3 = S[nb][3] * scale;
                if (do_mask) {
                    if (c0     > row_lo) v0 = -1e30f;
                    if (c0 + 1 > row_lo) v1 = -1e30f;
                    if (c0     > row_hi) v2 = -1e30f;
                    if (c0 + 1 > row_hi) v3 = -1e30f;
                }
                S[nb][0] = v0; S[nb][1] = v1; S[nb][2] = v2; S[nb][3] = v3;
                tmx_lo = fmaxf(tmx_lo, fmaxf(v0, v1));
                tmx_hi = fmaxf(tmx_hi, fmaxf(v2, v3));
            }
            tmx_lo = fmaxf(tmx_lo, __shfl_xor_sync(0xffffffffu, tmx_lo, 1));
            tmx_lo = fmaxf(tmx_lo, __shfl_xor_sync(0xffffffffu, tmx_lo, 2));
            tmx_hi = fmaxf(tmx_hi, __shfl_xor_sync(0xffffffffu, tmx_hi, 1));
            tmx_hi = fmaxf(tmx_hi, __shfl_xor_sync(0xffffffffu, tmx_hi, 2));
            float mn_lo = fmaxf(m_lo, tmx_lo), mn_hi = fmaxf(m_hi, tmx_hi);
            float a_lo = __expf(m_lo - mn_lo), a_hi = __expf(m_hi - mn_hi);
            m_lo = mn_lo; m_hi = mn_hi;
            float s_lo = 0.f, s_hi = 0.f;
#pragma unroll
            for (int nb = 0; nb < 8; ++nb) {
                S[nb][0] = __expf(S[nb][0] - mn_lo);
                S[nb][1] = __expf(S[nb][1] - mn_lo);
                S[nb][2] = __expf(S[nb][2] - mn_hi);
                S[nb][3] = __expf(S[nb][3] - mn_hi);
                s_lo += S[nb][0] + S[nb][1];
                s_hi += S[nb][2] + S[nb][3];
            }
            s_lo += __shfl_xor_sync(0xffffffffu, s_lo, 1);
            s_lo += __shfl_xor_sync(0xffffffffu, s_lo, 2);
            s_hi += __shfl_xor_sync(0xffffffffu, s_hi, 1);
            s_hi += __shfl_xor_sync(0xffffffffu, s_hi, 2);
            l_lo = l_lo * a_lo + s_lo;
            l_hi = l_hi * a_hi + s_hi;
#pragma unroll
            for (int nb = 0; nb < 16; ++nb) {
                O[nb][0] *= a_lo; O[nb][1] *= a_lo;
                O[nb][2] *= a_hi; O[nb][3] *= a_hi;
            }

            uint32_t ph[4][4], pl[4][4];
#pragma unroll
            for (int kb = 0; kb < 4; ++kb) {
#pragma unroll
                for (int hf = 0; hf < 2; ++hf) {
                    int nb = 2 * kb + hf;
                    __nv_bfloat162 h01 = __floats2bfloat162_rn(S[nb][0], S[nb][1]);
                    __nv_bfloat162 h23 = __floats2bfloat162_rn(S[nb][2], S[nb][3]);
                    __nv_bfloat162 l01 = __floats2bfloat162_rn(
                        S[nb][0] - __low2float(h01), S[nb][1] - __high2float(h01));
                    __nv_bfloat162 l23 = __floats2bfloat162_rn(
                        S[nb][2] - __low2float(h23), S[nb][3] - __high2float(h23));
                    ph[kb][2 * hf]     = bf2u(h01);
                    ph[kb][2 * hf + 1] = bf2u(h23);
                    pl[kb][2 * hf]     = bf2u(l01);
                    pl[kb][2 * hf + 1] = bf2u(l23);
                }
            }

#pragma unroll
            for (int kb = 0; kb < 4; ++kb) {
#pragma unroll
                for (int np2 = 0; np2 < 8; ++np2) {
                    uint32_t vh[4], vl[4];
                    uint32_t va = ASWZ(kb * 16 + rit, np2 * 2 + chalf);
                    ldsm4t(vh, sV + va);
                    ldsm4t(vl, sV + 16384u + va);
                    uint32_t bh0[2] = {vh[0], vh[1]}, bh1[2] = {vh[2], vh[3]};
                    uint32_t bl0[2] = {vl[0], vl[1]}, bl1[2] = {vl[2], vl[3]};
                    mma16816(O[2 * np2],     ph[kb], bh0);
                    mma16816(O[2 * np2],     ph[kb], bl0);
                    mma16816(O[2 * np2],     pl[kb], bh0);
                    mma16816(O[2 * np2 + 1], ph[kb], bh1);
                    mma16816(O[2 * np2 + 1], ph[kb], bl1);
                    mma16816(O[2 * np2 + 1], pl[kb], bh1);
                }
            }
        }
        __syncthreads();
    }

    // epilogue: fp16 AO [Mm, 2048]
    float i_lo = 1.f / l_lo, i_hi = 1.f / l_hi;
#pragma unroll
    for (int nb = 0; nb < 16; ++nb) {
        float v0 = O[nb][0] * i_lo, v1 = O[nb][1] * i_lo;
        float v2 = O[nb][2] * i_hi, v3 = O[nb][3] * i_hi;
        size_t o_lo = (size_t)(b * Ss + row_lo) * Dd + h * HDd + nb * 8 + tq * 2;
        size_t o_hi = o_lo + 8 * (size_t)Dd;
        __half2 a01 = __floats2half2_rn(v0, v1);
        __half2 a23 = __floats2half2_rn(v2, v3);
        *(uint32_t*)(AO16 + o_lo) = *(uint32_t*)&a01;
        *(uint32_t*)(AO16 + o_hi) = *(uint32_t*)&a23;
    }
}

// ---------------------------------------------------------------------------
// Launch. Inputs: hidden_states, attention_mask, cos, sin, Wq, Wk, Wv, Wo
// ---------------------------------------------------------------------------
extern "C" void kernel_launch(void* const* d_in, const int* in_sizes, int n_in,
                              void* d_out, int out_size)
{
    const float* X  = (const float*)d_in[0];
    const float* cs = (const float*)d_in[2];
    const float* sn = (const float*)d_in[3];
    const float* Wq = (const float*)d_in[4];
    const float* Wk = (const float*)d_in[5];
    const float* Wv = (const float*)d_in[6];
    const float* Wo = (const float*)d_in[7];
    float* out = (float*)d_out;

    __nv_bfloat16 *xhi, *xlo, *wqh, *wql, *wkh, *wkl, *wvh, *wvl;
    __nv_bfloat16 *qhi, *qlo, *khi, *klo, *vhi, *vlo;
    __half *wot16, *ao16;
    cudaGetSymbolAddress((void**)&xhi, g_xhi);
    cudaGetSymbolAddress((void**)&xlo, g_xlo);
    cudaGetSymbolAddress((void**)&wqh, g_wqt_hi);
    cudaGetSymbolAddress((void**)&wql, g_wqt_lo);
    cudaGetSymbolAddress((void**)&wkh, g_wkt_hi);
    cudaGetSymbolAddress((void**)&wkl, g_wkt_lo);
    cudaGetSymbolAddress((void**)&wvh, g_wvt_hi);
    cudaGetSymbolAddress((void**)&wvl, g_wvt_lo);
    cudaGetSymbolAddress((void**)&wot16, g_wot16);
    cudaGetSymbolAddress((void**)&qhi, g_qhi);
    cudaGetSymbolAddress((void**)&qlo, g_qlo);
    cudaGetSymbolAddress((void**)&khi, g_khi);
    cudaGetSymbolAddress((void**)&klo, g_klo);
    cudaGetSymbolAddress((void**)&vhi, g_vhi);
    cudaGetSymbolAddress((void**)&vlo, g_vlo);
    cudaGetSymbolAddress((void**)&ao16, g_ao16);

    cudaFuncSetAttribute(qkv_gemm, cudaFuncAttributeMaxDynamicSharedMemorySize, G2SMEM_BYTES);
    cudaFuncSetAttribute(o_gemm16, cudaFuncAttributeMaxDynamicSharedMemorySize, H_SMEM_BYTES);
    cudaFuncSetAttribute(flash_attn_mma, cudaFuncAttributeMaxDynamicSharedMemorySize, ASMEM_BYTES);

    // Fused weight transpose/convert + X split
    transpose_all<<<10240, dim3(32, 8)>>>(Wq, Wk, Wv, Wo);
    {
        int nx = Mm * Dd;
        split_fp32<<<(nx + 255) / 256, 256>>>(X, xhi, xlo, nx);
    }

    // Fused QKV projection (+RoPE for Q/K, split outputs)
    qkv_gemm<<<dim3(24, Mm / 256), 256, G2SMEM_BYTES>>>(
        (const uint4*)xhi, (const uint4*)xlo,
        (const uint4*)wqh, (const uint4*)wql,
        (const uint4*)wkh, (const uint4*)wkl,
        (const uint4*)wvh, (const uint4*)wvl,
        qhi, qlo, khi, klo, vhi, vlo, cs, sn);

    // Attention (tensor-core, split bf16), writes fp16 AO
    flash_attn_mma<<<dim3(Ss / 128, Hh, Bb), 256, ASMEM_BYTES>>>(
        qhi, qlo, khi, klo, vhi, vlo, ao16);

    // Output projection (fp16 single-product) -> fp32 out
    o_gemm16<<<dim3(Dd / 128, Mm / 256), 256, H_SMEM_BYTES>>>(
        (const uint4*)ao16, (const uint4*)wot16, out);
}

// round 14
// speedup vs baseline: 5.2305x; 1.2770x over previous
#include <cuda_runtime.h>
#include <cuda_bf16.h>
#include <cuda_fp16.h>
#include <math.h>
#include <stdint.h>

// Problem constants
#define Bb   2
#define Ss   2048
#define Dd   2048
#define Hh   16
#define KVHh 4
#define HDd  128
#define Mm   (Bb * Ss)   // 4096

// ---------------------------------------------------------------------------
// Scratch (device globals). 16B-aligned (vector access).
// ---------------------------------------------------------------------------
__device__ __align__(16) __nv_bfloat16 g_xhi[(size_t)Mm * Dd];
__device__ __align__(16) __nv_bfloat16 g_xlo[(size_t)Mm * Dd];
__device__ __align__(16) __nv_bfloat16 g_wqt_hi[(size_t)Dd * Dd];
__device__ __align__(16) __nv_bfloat16 g_wqt_lo[(size_t)Dd * Dd];
__device__ __align__(16) __nv_bfloat16 g_wkt_hi[(size_t)(KVHh*HDd) * Dd];
__device__ __align__(16) __nv_bfloat16 g_wkt_lo[(size_t)(KVHh*HDd) * Dd];
__device__ __align__(16) __nv_bfloat16 g_wvt_hi[(size_t)(KVHh*HDd) * Dd];
__device__ __align__(16) __nv_bfloat16 g_wvt_lo[(size_t)(KVHh*HDd) * Dd];
__device__ __align__(16) __half        g_wot16[(size_t)Dd * Dd];    // Wo^T fp16

__device__ __align__(16) __half g_q16[(size_t)Mm * Hh   * HDd];
__device__ __align__(16) __half g_k16[(size_t)Mm * KVHh * HDd];
__device__ __align__(16) __half g_v16[(size_t)Mm * KVHh * HDd];
__device__ __align__(16) __half g_ao16[(size_t)Mm * Dd];            // attention out fp16

// ---------------------------------------------------------------------------
// Helpers (plain PTX, nothing sm_103a-gated)
// ---------------------------------------------------------------------------
__device__ __forceinline__ uint32_t smem_u32(const void* p) {
    uint32_t a;
    asm("{ .reg .u64 t; cvta.to.shared.u64 t, %1; cvt.u32.u64 %0, t; }"
        : "=r"(a) : "l"(p));
    return a;
}
__device__ __forceinline__ void cp_async16(uint32_t dst, const void* src) {
    asm volatile("cp.async.cg.shared.global [%0], [%1], 16;" :: "r"(dst), "l"(src));
}
#define CP_COMMIT()  asm volatile("cp.async.commit_group;" ::: "memory")
#define CP_WAIT(n)   asm volatile("cp.async.wait_group %0;" :: "n"(n) : "memory")

__device__ __forceinline__ void ldsm4(uint32_t* r, uint32_t addr) {
    asm volatile("ldmatrix.sync.aligned.m8n8.x4.shared.b16 {%0,%1,%2,%3}, [%4];"
        : "=r"(r[0]), "=r"(r[1]), "=r"(r[2]), "=r"(r[3]) : "r"(addr));
}
__device__ __forceinline__ void ldsm4t(uint32_t* r, uint32_t addr) {
    asm volatile("ldmatrix.sync.aligned.m8n8.x4.trans.shared.b16 {%0,%1,%2,%3}, [%4];"
        : "=r"(r[0]), "=r"(r[1]), "=r"(r[2]), "=r"(r[3]) : "r"(addr));
}
__device__ __forceinline__ void mma16816(float* d, const uint32_t* a, const uint32_t* b) {
    asm volatile(
        "mma.sync.aligned.m16n8k16.row.col.f32.bf16.bf16.f32 "
        "{%0,%1,%2,%3}, {%4,%5,%6,%7}, {%8,%9}, {%0,%1,%2,%3};"
        : "+f"(d[0]), "+f"(d[1]), "+f"(d[2]), "+f"(d[3])
        : "r"(a[0]), "r"(a[1]), "r"(a[2]), "r"(a[3]), "r"(b[0]), "r"(b[1]));
}
__device__ __forceinline__ void mma16816h(float* d, const uint32_t* a, const uint32_t* b) {
    asm volatile(
        "mma.sync.aligned.m16n8k16.row.col.f32.f16.f16.f32 "
        "{%0,%1,%2,%3}, {%4,%5,%6,%7}, {%8,%9}, {%0,%1,%2,%3};"
        : "+f"(d[0]), "+f"(d[1]), "+f"(d[2]), "+f"(d[3])
        : "r"(a[0]), "r"(a[1]), "r"(a[2]), "r"(a[3]), "r"(b[0]), "r"(b[1]));
}
__device__ __forceinline__ uint32_t bf2u(__nv_bfloat162 v) {
    return *reinterpret_cast<uint32_t*>(&v);
}
__device__ __forceinline__ uint32_t h2u(__half2 v) {
    return *reinterpret_cast<uint32_t*>(&v);
}

// ---------------------------------------------------------------------------
// Split fp32 -> (hi, lo) bf16  (X input)
// ---------------------------------------------------------------------------
__global__ void split_fp32(const float* __restrict__ in,
                           __nv_bfloat16* __restrict__ hi,
                           __nv_bfloat16* __restrict__ lo, int n)
{
    int i = blockIdx.x * blockDim.x + threadIdx.x;
    if (i >= n) return;
    float v = in[i];
    __nv_bfloat16 h = __float2bfloat16(v);
    hi[i] = h;
    lo[i] = __float2bfloat16(v - __bfloat162float(h));
}

// ---------------------------------------------------------------------------
// Fused weight transpose (one launch): Wq/Wk/Wv -> split-bf16 [N,K];
// Wo -> fp16 [N,K].
// ---------------------------------------------------------------------------
__global__ __launch_bounds__(256) void transpose_all(
    const float* __restrict__ Wq, const float* __restrict__ Wk,
    const float* __restrict__ Wv, const float* __restrict__ Wo)
{
    __shared__ float t[32][33];
    int b = blockIdx.x;
    const float* in;
    __nv_bfloat16 *hiT = nullptr, *loT = nullptr;
    __half* h16 = nullptr;
    int N, nb, kb;
    if (b < 4096)      { in = Wq; hiT = g_wqt_hi; loT = g_wqt_lo; N = 2048; nb = b & 63; kb = b >> 6; }
    else if (b < 5120) { b -= 4096; in = Wk; hiT = g_wkt_hi; loT = g_wkt_lo; N = 512; nb = b & 15; kb = b >> 4; }
    else if (b < 6144) { b -= 5120; in = Wv; hiT = g_wvt_hi; loT = g_wvt_lo; N = 512; nb = b & 15; kb = b >> 4; }
    else               { b -= 6144; in = Wo; h16 = g_wot16; N = 2048; nb = b & 63; kb = b >> 6; }

    int n0 = nb * 32, k0 = kb * 32;
    int tx = threadIdx.x, ty = threadIdx.y;  // 32 x 8
#pragma unroll
    for (int i = 0; i < 32; i += 8)
        t[ty + i][tx] = in[(size_t)(k0 + ty + i) * N + n0 + tx];
    __syncthreads();
#pragma unroll
    for (int i = 0; i < 32; i += 8) {
        float v = t[tx][ty + i];
        size_t o = (size_t)(n0 + ty + i) * 2048 + k0 + tx;
        if (h16) {
            h16[o] = __float2half(v);
        } else {
            __nv_bfloat16 h = __float2bfloat16(v);
            hiT[o] = h;
            loT[o] = __float2bfloat16(v - __bfloat162float(h));
        }
    }
}

// ---------------------------------------------------------------------------
// GEMM core (split-bf16 3-product): CTA 256x128, warp 64x64, BK=64, 2 stages.
// ---------------------------------------------------------------------------
#define ST_ALO 32768u
#define ST_BHI 65536u
#define ST_BLO 81920u
#define QSTAGE 98304u
#define G2SMEM_BYTES 196608

__device__ __forceinline__ void gemm_core_256x128(
    uint32_t sb,
    const uint4* __restrict__ A0, const uint4* __restrict__ A1,
    const uint4* __restrict__ B0, const uint4* __restrict__ B1,
    int arow0, float D[4][8][4])
{
    const int tid = threadIdx.x, lane = tid & 31, wid = tid >> 5;
    const int m0 = (wid >> 1) * 64, n0 = (wid & 1) * 64;
    const int r_ld = tid >> 3, c_ld = tid & 7;

    auto issue = [&](int it) {
        const uint32_t st = sb + (uint32_t)(it & 1) * QSTAGE;
        const int kc = it * 8;
#pragma unroll
        for (int g = 0; g < 8; ++g) {
            const int r = r_ld + 32 * g;
            const uint32_t d = st + (uint32_t)r * 128u
                             + ((uint32_t)(c_ld ^ (r & 7)) << 4);
            const size_t ia = (size_t)(arow0 + r) * 256 + kc + c_ld;
            cp_async16(d,          A0 + ia);
            cp_async16(d + ST_ALO, A1 + ia);
            if (g < 4) {
                const size_t ib = (size_t)r * 256 + kc + c_ld;
                cp_async16(d + ST_BHI, B0 + ib);
                cp_async16(d + ST_BLO, B1 + ib);
            }
        }
        CP_COMMIT();
    };

#pragma unroll
    for (int i = 0; i < 4; ++i)
#pragma unroll
        for (int j = 0; j < 8; ++j)
#pragma unroll
            for (int x = 0; x < 4; ++x) D[i][j][x] = 0.f;

    issue(0);

    const int a_rowit = (lane & 7) + ((lane >> 3) & 1) * 8;
    const int a_cb    = lane >> 4;
    const int b_rowit = (lane & 7) + ((lane >> 4) << 3);
    const int b_cb    = (lane >> 3) & 1;

    const int nk = 2048 / 64;
    for (int c = 0; c < nk; ++c) {
        if (c + 1 < nk) { issue(c + 1); CP_WAIT(1); }
        else            { CP_WAIT(0); }
        __syncthreads();
        const uint32_t base = sb + (uint32_t)(c & 1) * QSTAGE;

#pragma unroll
        for (int ks = 0; ks < 4; ++ks) {
            uint32_t ah[4][4], al[4][4];
            const int acb = ks * 2 + a_cb;
#pragma unroll
            for (int i = 0; i < 4; ++i) {
                const int r = m0 + 16 * i + a_rowit;
                const uint32_t ad = base + (uint32_t)r * 128u
                                  + ((uint32_t)(acb ^ (r & 7)) << 4);
                ldsm4(ah[i], ad);
                ldsm4(al[i], ad + ST_ALO);
            }
            const int bcb = ks * 2 + b_cb;
#pragma unroll
            for (int jh = 0; jh < 2; ++jh) {
                uint32_t bh[2][4], bl[2][4];
#pragma unroll
                for (int j2 = 0; j2 < 2; ++j2) {
                    const int r = n0 + 16 * (2 * jh + j2) + b_rowit;
                    const uint32_t bd = base + (uint32_t)r * 128u
                                      + ((uint32_t)(bcb ^ (r & 7)) << 4);
                    ldsm4(bh[j2], bd + ST_BHI);
                    ldsm4(bl[j2], bd + ST_BLO);
                }
#pragma unroll
                for (int i = 0; i < 4; ++i)
#pragma unroll
                    for (int j2 = 0; j2 < 2; ++j2) {
                        const int j = 2 * jh + j2;
                        mma16816(D[i][2 * j],     ah[i], bh[j2]);
                        mma16816(D[i][2 * j],     ah[i], bl[j2]);
                        mma16816(D[i][2 * j],     al[i], bh[j2]);
                        mma16816(D[i][2 * j + 1], ah[i], bh[j2] + 2);
                        mma16816(D[i][2 * j + 1], ah[i], bl[j2] + 2);
                        mma16816(D[i][2 * j + 1], al[i], bh[j2] + 2);
                    }
            }
        }
        __syncthreads();
    }
}

// ---------------------------------------------------------------------------
// Fused QKV projection + RoPE epilogue -> fp16 Q/K/V.
// Grid: (24, Mm/256). u<16: Q head u (rope). u<20: K head u-16 (rope).
// u>=20: V head u-20.
// ---------------------------------------------------------------------------
__global__ __launch_bounds__(256) void qkv_gemm(
    const uint4* __restrict__ xhi, const uint4* __restrict__ xlo,
    const uint4* __restrict__ wqh, const uint4* __restrict__ wql,
    const uint4* __restrict__ wkh, const uint4* __restrict__ wkl,
    const uint4* __restrict__ wvh, const uint4* __restrict__ wvl,
    __half* __restrict__ q16, __half* __restrict__ k16, __half* __restrict__ v16,
    const float* __restrict__ cs, const float* __restrict__ sn)
{
    extern __shared__ char smr[];
    const uint32_t sb = smem_u32(smr);
    const int u = blockIdx.x;
    const int arow0 = blockIdx.y * 256;

    const uint4 *B0, *B1;
    if (u < 16)      { B0 = wqh + (size_t)u * 32768;        B1 = wql + (size_t)u * 32768; }
    else if (u < 20) { B0 = wkh + (size_t)(u - 16) * 32768; B1 = wkl + (size_t)(u - 16) * 32768; }
    else             { B0 = wvh + (size_t)(u - 20) * 32768; B1 = wvl + (size_t)(u - 20) * 32768; }

    float D[4][8][4];
    gemm_core_256x128(sb, xhi, xlo, B0, B1, arow0, D);

    const int lane = threadIdx.x & 31, wid = threadIdx.x >> 5;
    const int m0 = (wid >> 1) * 64, n0 = (wid & 1) * 64;
    const int quad = lane >> 2, tq = lane & 3;

    if (u < 20) {
        __half* OQ; int W, head;
        if (u < 16) { OQ = q16; W = Hh * HDd;   head = u; }
        else        { OQ = k16; W = KVHh * HDd; head = u - 16; }
#pragma unroll
        for (int i = 0; i < 4; ++i) {
            const int rr = arow0 + m0 + 16 * i + quad;
#pragma unroll
            for (int jn = 0; jn < 8; ++jn) {
                const int ir = (n0 >> 1) + 4 * jn + tq;   // rope index 0..63
#pragma unroll
                for (int hh = 0; hh < 2; ++hh) {
                    const int r = rr + 8 * hh;
                    const float x0 = D[i][jn][2 * hh];
                    const float x1 = D[i][jn][2 * hh + 1];
                    const float cv = cs[(r & (Ss - 1)) * 64 + ir];
                    const float sv = sn[(r & (Ss - 1)) * 64 + ir];
                    const size_t bs = (size_t)r * W + head * HDd;
                    OQ[bs + ir]      = __float2half(x0 * cv - x1 * sv);
                    OQ[bs + 64 + ir] = __float2half(x1 * cv + x0 * sv);
                }
            }
        }
    } else {
        const int head = u - 20, W = KVHh * HDd;
#pragma unroll
        for (int i = 0; i < 4; ++i) {
            const int rr = arow0 + m0 + 16 * i + quad;
#pragma unroll
            for (int jn = 0; jn < 8; ++jn) {
                const int cc = head * HDd + n0 + 8 * jn + 2 * tq;
#pragma unroll
                for (int hh = 0; hh < 2; ++hh) {
                    const int r = rr + 8 * hh;
                    __half2 p = __floats2half2_rn(D[i][jn][2 * hh], D[i][jn][2 * hh + 1]);
                    *(uint32_t*)(v16 + (size_t)r * W + cc) = h2u(p);
                }
            }
        }
    }
}

// ---------------------------------------------------------------------------
// Output projection, fp16 single-product (R13-verified).
// ---------------------------------------------------------------------------
#define HSTG_B 32768u
#define HSTAGE 49152u
#define H_SMEM_BYTES 98304

__global__ __launch_bounds__(256) void o_gemm16(
    const uint4* __restrict__ A0, const uint4* __restrict__ W0,
    float* __restrict__ out)
{
    extern __shared__ char smr[];
    const uint32_t sb = smem_u32(smr);
    const int tid = threadIdx.x, lane = tid & 31, wid = tid >> 5;
    const int col0 = blockIdx.x * 128;
    const int arow0 = blockIdx.y * 256;
    const uint4* B0 = W0 + (size_t)col0 * 256;

    const int m0 = (wid >> 1) * 64, n0 = (wid & 1) * 64;
    const int r_ld = tid >> 3, c_ld = tid & 7;

    auto issue = [&](int it) {
        const uint32_t st = sb + (uint32_t)(it & 1) * HSTAGE;
        const int kc = it * 8;
#pragma unroll
        for (int g = 0; g < 8; ++g) {
            const int r = r_ld + 32 * g;
            const uint32_t d = st + (uint32_t)r * 128u
                             + ((uint32_t)(c_ld ^ (r & 7)) << 4);
            cp_async16(d, A0 + (size_t)(arow0 + r) * 256 + kc + c_ld);
            if (g < 4)
                cp_async16(d + HSTG_B, B0 + (size_t)r * 256 + kc + c_ld);
        }
        CP_COMMIT();
    };

    float D[4][8][4];
#pragma unroll
    for (int i = 0; i < 4; ++i)
#pragma unroll
        for (int j = 0; j < 8; ++j)
#pragma unroll
            for (int x = 0; x < 4; ++x) D[i][j][x] = 0.f;

    issue(0);

    const int a_rowit = (lane & 7) + ((lane >> 3) & 1) * 8;
    const int a_cb    = lane >> 4;
    const int b_rowit = (lane & 7) + ((lane >> 4) << 3);
    const int b_cb    = (lane >> 3) & 1;

    const int nk = 2048 / 64;
    for (int c = 0; c < nk; ++c) {
        if (c + 1 < nk) { issue(c + 1); CP_WAIT(1); }
        else            { CP_WAIT(0); }
        __syncthreads();
        const uint32_t base = sb + (uint32_t)(c & 1) * HSTAGE;

#pragma unroll
        for (int ks = 0; ks < 4; ++ks) {
            uint32_t ah[4][4];
            const int acb = ks * 2 + a_cb;
#pragma unroll
            for (int i = 0; i < 4; ++i) {
                const int r = m0 + 16 * i + a_rowit;
                ldsm4(ah[i], base + (uint32_t)r * 128u
                             + ((uint32_t)(acb ^ (r & 7)) << 4));
            }
            const int bcb = ks * 2 + b_cb;
#pragma unroll
            for (int jh = 0; jh < 2; ++jh) {
                uint32_t bh[2][4];
#pragma unroll
                for (int j2 = 0; j2 < 2; ++j2) {
                    const int r = n0 + 16 * (2 * jh + j2) + b_rowit;
                    ldsm4(bh[j2], base + HSTG_B + (uint32_t)r * 128u
                                  + ((uint32_t)(bcb ^ (r & 7)) << 4));
                }
#pragma unroll
                for (int i = 0; i < 4; ++i)
#pragma unroll
                    for (int j2 = 0; j2 < 2; ++j2) {
                        const int j = 2 * jh + j2;
                        mma16816h(D[i][2 * j],     ah[i], bh[j2]);
                        mma16816h(D[i][2 * j + 1], ah[i], bh[j2] + 2);
                    }
            }
        }
        __syncthreads();
    }

    const int quad = lane >> 2, tq = lane & 3;
#pragma unroll
    for (int i = 0; i < 4; ++i) {
        const int r = arow0 + m0 + 16 * i + quad;
#pragma unroll
        for (int jn = 0; jn < 8; ++jn) {
            const int cc = col0 + n0 + 8 * jn + 2 * tq;
            *(float2*)&out[(size_t)r * Dd + cc]       = make_float2(D[i][jn][0], D[i][jn][1]);
            *(float2*)&out[(size_t)(r + 8) * Dd + cc] = make_float2(D[i][jn][2], D[i][jn][3]);
        }
    }
}

// ---------------------------------------------------------------------------
// Flash attention, all-fp16 single-product. Causal, GQA.
// CTA: q-tile 128 rows, 256 threads (8 warps x m16). KV tiles 64, dbl-buffered.
// Smem: Q 32K | stage(K 16K + V 16K) x2 = 96KB total -> 2 CTAs/SM.
// ---------------------------------------------------------------------------
#define ASWZ(r, c) ((uint32_t)(r) * 256u + ((uint32_t)((c) ^ ((r) & 7)) << 4))
#define ASM_STAGE 32768u
#define AKV_STAGE 32768u
#define ASMEM_BYTES 98304

__global__ __launch_bounds__(256, 2) void flash_attn_f16(
    const __half* __restrict__ Q16, const __half* __restrict__ K16,
    const __half* __restrict__ V16, __half* __restrict__ AO16)
{
    extern __shared__ char sm[];
    const uint32_t sb = smem_u32(sm);
    const int tid = threadIdx.x, lane = tid & 31, wid = tid >> 5;
    const int qt = (int)gridDim.x - 1 - (int)blockIdx.x;   // heavy tiles first
    const int h = blockIdx.y, b = blockIdx.z, kvh = h >> 2;
    const int q0 = qt * 128;
    const int m0 = wid * 16;
    const int nkt = 2 * qt + 2;

    const int c_ld = tid & 15, r_ld = tid >> 4;

    // Q tile (128 x 128 fp16)
#pragma unroll
    for (int i = 0; i < 8; ++i) {
        int r = r_ld + 16 * i;
        size_t g = ((size_t)((b * Ss + q0 + r) * Hh + h)) * HDd + c_ld * 8;
        cp_async16(sb + ASWZ(r, c_ld), Q16 + g);
    }
    auto issue_kv = [&](int kt) {
        uint32_t st = sb + ASM_STAGE + (uint32_t)(kt & 1) * AKV_STAGE;
        int kbase = kt * 64;
#pragma unroll
        for (int i = 0; i < 4; ++i) {
            int r = r_ld + 16 * i;
            size_t g = ((size_t)((b * Ss + kbase + r) * KVHh + kvh)) * HDd + c_ld * 8;
            uint32_t d = ASWZ(r, c_ld);
            cp_async16(st + d,          K16 + g);
            cp_async16(st + 16384u + d, V16 + g);
        }
    };
    issue_kv(0);
    CP_COMMIT();

    float O[16][4];
#pragma unroll
    for (int i = 0; i < 16; ++i)
#pragma unroll
        for (int x = 0; x < 4; ++x) O[i][x] = 0.f;
    float m_lo = -1e30f, m_hi = -1e30f, l_lo = 0.f, l_hi = 0.f;

    const int quad = lane >> 2, tq = lane & 3;
    const int rit = lane & 15;
    const int chalf = lane >> 4;
    const int row_lo = q0 + m0 + quad;
    const int row_hi = row_lo + 8;
    const float scale = 0.08838834764831845f;

    for (int kt = 0; kt < nkt; ++kt) {
        if (kt + 1 < nkt) { issue_kv(kt + 1); CP_COMMIT(); CP_WAIT(1); }
        else              { CP_WAIT(0); }
        __syncthreads();

        const int kbase = kt * 64;
        if (kbase <= q0 + m0 + 15) {
            const uint32_t sK = sb + ASM_STAGE + (uint32_t)(kt & 1) * AKV_STAGE;
            const uint32_t sV = sK + 16384u;

            float S[8][4];
#pragma unroll
            for (int i = 0; i < 8; ++i)
#pragma unroll
                for (int x = 0; x < 4; ++x) S[i][x] = 0.f;

            // S = Q K^T (fp16 single)
#pragma unroll
            for (int k16 = 0; k16 < 8; ++k16) {
                uint32_t qf[4];
                ldsm4(qf, sb + ASWZ(m0 + rit, k16 * 2 + chalf));
#pragma unroll
                for (int np = 0; np < 4; ++np) {
                    uint32_t kf[4];
                    ldsm4(kf, sK + ASWZ(np * 16 + rit, k16 * 2 + chalf));
                    uint32_t b0[2] = {kf[0], kf[2]}, b1[2] = {kf[1], kf[3]};
                    mma16816h(S[2 * np],     qf, b0);
                    mma16816h(S[2 * np + 1], qf, b1);
                }
            }

            // online softmax
            const bool do_mask = (kt >= nkt - 2);
            float tmx_lo = -1e30f, tmx_hi = -1e30f;
#pragma unroll
            for (int nb = 0; nb < 8; ++nb) {
                int c0 = kbase + nb * 8 + tq * 2;
                float v0 = S[nb][0] * scale, v1 = S[nb][1] * scale;
                float v2 = S[nb][2] * scale, v3 = S[nb][3] * scale;
                if (do_mask) {
                    if (c0     > row_lo) v0 = -1e30f;
                    if (c0 + 1 > row_lo) v1 = -1e30f;
                    if (c0     > row_hi) v2 = -1e30f;
                    if (c0 + 1 > row_hi) v3 = -1e30f;
                }
                S[nb][0] = v0; S[nb][1] = v1; S[nb][2] = v2; S[nb][3] = v3;
                tmx_lo = fmaxf(tmx_lo, fmaxf(v0, v1));
                tmx_hi = fmaxf(tmx_hi, fmaxf(v2, v3));
            }
            tmx_lo = fmaxf(tmx_lo, __shfl_xor_sync(0xffffffffu, tmx_lo, 1));
            tmx_lo = fmaxf(tmx_lo, __shfl_xor_sync(0xffffffffu, tmx_lo, 2));
            tmx_hi = fmaxf(tmx_hi, __shfl_xor_sync(0xffffffffu, tmx_hi, 1));
            tmx_hi = fmaxf(tmx_hi, __shfl_xor_sync(0xffffffffu, tmx_hi, 2));
            float mn_lo = fmaxf(m_lo, tmx_lo), mn_hi = fmaxf(m_hi, tmx_hi);
            float a_lo = __expf(m_lo - mn_lo), a_hi = __expf(m_hi - mn_hi);
            m_lo = mn_lo; m_hi = mn_hi;
            float s_lo = 0.f, s_hi = 0.f;
#pragma unroll
            for (int nb = 0; nb < 8; ++nb) {
                S[nb][0] = __expf(S[nb][0] - mn_lo);
                S[nb][1] = __expf(S[nb][1] - mn_lo);
                S[nb][2] = __expf(S[nb][2] - mn_hi);
                S[nb][3] = __expf(S[nb][3] - mn_hi);
                s_lo += S[nb][0] + S[nb][1];
                s_hi += S[nb][2] + S[nb][3];
            }
            s_lo += __shfl_xor_sync(0xffffffffu, s_lo, 1);
            s_lo += __shfl_xor_sync(0xffffffffu, s_lo, 2);
            s_hi += __shfl_xor_sync(0xffffffffu, s_hi, 1);
            s_hi += __shfl_xor_sync(0xffffffffu, s_hi, 2);
            l_lo = l_lo * a_lo + s_lo;
            l_hi = l_hi * a_hi + s_hi;
#pragma unroll
            for (int nb = 0; nb < 16; ++nb) {
                O[nb][0] *= a_lo; O[nb][1] *= a_lo;
                O[nb][2] *= a_hi; O[nb][3] *= a_hi;
            }

            // P fragments (fp16)
            uint32_t ph[4][4];
#pragma unroll
            for (int kb = 0; kb < 4; ++kb) {
#pragma unroll
                for (int hf = 0; hf < 2; ++hf) {
                    int nb = 2 * kb + hf;
                    ph[kb][2 * hf]     = h2u(__floats2half2_rn(S[nb][0], S[nb][1]));
                    ph[kb][2 * hf + 1] = h2u(__floats2half2_rn(S[nb][2], S[nb][3]));
                }
            }

            // O += P V (fp16 single, V via ldmatrix.trans)
#pragma unroll
            for (int kb = 0; kb < 4; ++kb) {
#pragma unroll
                for (int np2 = 0; np2 < 8; ++np2) {
                    uint32_t vf[4];
                    ldsm4t(vf, sV + ASWZ(kb * 16 + rit, np2 * 2 + chalf));
                    uint32_t b0[2] = {vf[0], vf[1]}, b1[2] = {vf[2], vf[3]};
                    mma16816h(O[2 * np2],     ph[kb], b0);
                    mma16816h(O[2 * np2 + 1], ph[kb], b1);
                }
            }
        }
        __syncthreads();
    }

    // epilogue: fp16 AO [Mm, 2048]
    float i_lo = 1.f / l_lo, i_hi = 1.f / l_hi;
#pragma unroll
    for (int nb = 0; nb < 16; ++nb) {
        float v0 = O[nb][0] * i_lo, v1 = O[nb][1] * i_lo;
        float v2 = O[nb][2] * i_hi, v3 = O[nb][3] * i_hi;
        size_t o_lo = (size_t)(b * Ss + row_lo) * Dd + h * HDd + nb * 8 + tq * 2;
        size_t o_hi = o_lo + 8 * (size_t)Dd;
        __half2 a01 = __floats2half2_rn(v0, v1);
        __half2 a23 = __floats2half2_rn(v2, v3);
        *(uint32_t*)(AO16 + o_lo) = h2u(a01);
        *(uint32_t*)(AO16 + o_hi) = h2u(a23);
    }
}

// ---------------------------------------------------------------------------
// Launch. Inputs: hidden_states, attention_mask, cos, sin, Wq, Wk, Wv, Wo
// ---------------------------------------------------------------------------
extern "C" void kernel_launch(void* const* d_in, const int* in_sizes, int n_in,
                              void* d_out, int out_size)
{
    const float* X  = (const float*)d_in[0];
    const float* cs = (const float*)d_in[2];
    const float* sn = (const float*)d_in[3];
    const float* Wq = (const float*)d_in[4];
    const float* Wk = (const float*)d_in[5];
    const float* Wv = (const float*)d_in[6];
    const float* Wo = (const float*)d_in[7];
    float* out = (float*)d_out;

    __nv_bfloat16 *xhi, *xlo, *wqh, *wql, *wkh, *wkl, *wvh, *wvl;
    __half *wot16, *q16, *k16, *v16, *ao16;
    cudaGetSymbolAddress((void**)&xhi, g_xhi);
    cudaGetSymbolAddress((void**)&xlo, g_xlo);
    cudaGetSymbolAddress((void**)&wqh, g_wqt_hi);
    cudaGetSymbolAddress((void**)&wql, g_wqt_lo);
    cudaGetSymbolAddress((void**)&wkh, g_wkt_hi);
    cudaGetSymbolAddress((void**)&wkl, g_wkt_lo);
    cudaGetSymbolAddress((void**)&wvh, g_wvt_hi);
    cudaGetSymbolAddress((void**)&wvl, g_wvt_lo);
    cudaGetSymbolAddress((void**)&wot16, g_wot16);
    cudaGetSymbolAddress((void**)&q16, g_q16);
    cudaGetSymbolAddress((void**)&k16, g_k16);
    cudaGetSymbolAddress((void**)&v16, g_v16);
    cudaGetSymbolAddress((void**)&ao16, g_ao16);

    cudaFuncSetAttribute(qkv_gemm, cudaFuncAttributeMaxDynamicSharedMemorySize, G2SMEM_BYTES);
    cudaFuncSetAttribute(o_gemm16, cudaFuncAttributeMaxDynamicSharedMemorySize, H_SMEM_BYTES);
    cudaFuncSetAttribute(flash_attn_f16, cudaFuncAttributeMaxDynamicSharedMemorySize, ASMEM_BYTES);

    // Fused weight transpose/convert + X split
    transpose_all<<<10240, dim3(32, 8)>>>(Wq, Wk, Wv, Wo);
    {
        int nx = Mm * Dd;
        split_fp32<<<(nx + 255) / 256, 256>>>(X, xhi, xlo, nx);
    }

    // Fused QKV projection (+RoPE for Q/K), fp16 outputs
    qkv_gemm<<<dim3(24, Mm / 256), 256, G2SMEM_BYTES>>>(
        (const uint4*)xhi, (const uint4*)xlo,
        (const uint4*)wqh, (const uint4*)wql,
        (const uint4*)wkh, (const uint4*)wkl,
        (const uint4*)wvh, (const uint4*)wvl,
        q16, k16, v16, cs, sn);

    // Attention (all-fp16 tensor core), writes fp16 AO
    flash_attn_f16<<<dim3(Ss / 128, Hh, Bb), 256, ASMEM_BYTES>>>(
        q16, k16, v16, ao16);

    // Output projection (fp16 single-product) -> fp32 out
    o_gemm16<<<dim3(Dd / 128, Mm / 256), 256, H_SMEM_BYTES>>>(
        (const uint4*)ao16, (const uint4*)wot16, out);
}